// round 14
// baseline (speedup 1.0000x reference)
#include <cuda_runtime.h>
#include <math.h>
#include <stdint.h>

#define B      16
#define C      256
#define HW     4096
#define MEM    64
#define NTOK   4160
#define H3     1536
#define HID    512
#define NHEADS 8
#define DH     64
#define NCHUNK 13
#define CHTOK  320     // NTOK / NCHUNK
#define NTILES 33      // gemm_qkv n-tiles

// -------- scratch (device globals, fully overwritten every launch) --------
__device__ float g_qkv[(size_t)B * H3 * NTOK];     // k rows 512..1023 hold exp(k); v rows 1024..1535
__device__ float g_ksump[NTILES * B * HID];        // per-n-tile partial sums of exp(k)
__device__ float g_kinv[B * HID];                  // 1 / total sum
__device__ float g_qexp[(size_t)B * HID * HW];     // softmaxed+scaled q (tf32-prerounded)
__device__ float g_ctxp[(size_t)NCHUNK * B * NHEADS * DH * DH];  // partial ctxT [ch][bh][e][d]
__device__ float g_ctxT[B * NHEADS * DH * DH];     // ctxT [bh][e][d], inv applied
__device__ float g_wc[(size_t)B * C * HID];        // folded weights (tf32-prerounded)

// ---------------- tf32 mma helpers ----------------
__device__ __forceinline__ uint32_t f2tf32(float f) {
    uint32_t r;
    asm("cvt.rna.tf32.f32 %0, %1;" : "=r"(r) : "f"(f));
    return r;
}

__device__ __forceinline__ void mma_tf32(float* d, const uint32_t* a, const uint32_t* b) {
    asm volatile(
        "mma.sync.aligned.m16n8k8.row.col.f32.tf32.tf32.f32 "
        "{%0,%1,%2,%3}, {%4,%5,%6,%7}, {%8,%9}, {%0,%1,%2,%3};\n"
        : "+f"(d[0]), "+f"(d[1]), "+f"(d[2]), "+f"(d[3])
        : "r"(a[0]), "r"(a[1]), "r"(a[2]), "r"(a[3]), "r"(b[0]), "r"(b[1]));
}

__device__ __forceinline__ void cp16(uint32_t dst, const void* src) {
    asm volatile("cp.async.cg.shared.global [%0], [%1], 16;\n" :: "r"(dst), "l"(src));
}
#define CP_COMMIT() asm volatile("cp.async.commit_group;\n")

// =====================================================================
// K1: qkv = W_qkv @ x_ext  (tf32 MMA) — kt=16, 2-stage double buffer,
// register staging, occ=2 preserved (40 KB smem). Fused epilogues:
// q softmax -> g_qexp (tf32-prerounded), exp(k)+partial sums, v store.
// =====================================================================
__global__ __launch_bounds__(256, 2) void gemm_qkv(
    const float* __restrict__ x, const float* __restrict__ mem,
    const float* __restrict__ W)
{
    __shared__ uint32_t As[2][128][20];   // [stage][m][k]  (bank: 4g+tg, conflict-free)
    __shared__ uint32_t Bs[2][16][136];   // [stage][k][n]
    __shared__ float psum[4][128];        // k partial sums [warp_n group][row]

    int b  = blockIdx.z;
    int m0 = blockIdx.y * 128;
    int n0 = blockIdx.x * 128;
    int tid  = threadIdx.x;
    int lane = tid & 31, wid = tid >> 5;
    int warp_m = (wid & 1) * 64;
    int warp_n = (wid >> 1) * 32;
    int g = lane >> 2, tg = lane & 3;

    const float* src;
    int stride, col0, ncols;
    if (n0 < HW) { src = x + (size_t)b * C * HW; stride = HW;  col0 = n0; ncols = 128; }
    else {
        if (m0 < HID) return;            // q not needed at memory tokens
        src = mem; stride = MEM; col0 = 0; ncols = MEM;
    }

    // per-thread addressing for loads (kt=16)
    int a_row0 = tid >> 2,        a_kc = (tid & 3) * 4;          // A: idx = tid (+256)
    int b_row0 = tid >> 5,        b_nc = (tid & 31) * 4;         // B: idx = tid (+256)

    float4 a_st[2], b_st[2];
    auto LOAD = [&](int k0) {
        a_st[0] = *(const float4*)(W + (size_t)(m0 + a_row0) * C + k0 + a_kc);
        a_st[1] = *(const float4*)(W + (size_t)(m0 + a_row0 + 64) * C + k0 + a_kc);
        b_st[0] = (b_nc + 3 < ncols)
            ? *(const float4*)(src + (size_t)(k0 + b_row0) * stride + col0 + b_nc)
            : make_float4(0.f, 0.f, 0.f, 0.f);
        b_st[1] = (b_nc + 3 < ncols)
            ? *(const float4*)(src + (size_t)(k0 + b_row0 + 8) * stride + col0 + b_nc)
            : make_float4(0.f, 0.f, 0.f, 0.f);
    };
    auto STORE = [&](int s) {
        #pragma unroll
        for (int r = 0; r < 2; r++) {
            int row = a_row0 + r * 64;
            As[s][row][a_kc + 0] = f2tf32(a_st[r].x);
            As[s][row][a_kc + 1] = f2tf32(a_st[r].y);
            As[s][row][a_kc + 2] = f2tf32(a_st[r].z);
            As[s][row][a_kc + 3] = f2tf32(a_st[r].w);
        }
        #pragma unroll
        for (int r = 0; r < 2; r++) {
            int row = b_row0 + r * 8;
            Bs[s][row][b_nc + 0] = f2tf32(b_st[r].x);
            Bs[s][row][b_nc + 1] = f2tf32(b_st[r].y);
            Bs[s][row][b_nc + 2] = f2tf32(b_st[r].z);
            Bs[s][row][b_nc + 3] = f2tf32(b_st[r].w);
        }
    };

    float acc[4][4][4];
    #pragma unroll
    for (int mf = 0; mf < 4; mf++)
        #pragma unroll
        for (int nf = 0; nf < 4; nf++)
            #pragma unroll
            for (int i = 0; i < 4; i++) acc[mf][nf][i] = 0.f;

    LOAD(0);
    STORE(0);
    __syncthreads();

    #pragma unroll 2
    for (int t = 0; t < 16; t++) {                  // 16 k-tiles of 16
        if (t < 15) LOAD((t + 1) * 16);
        int s = t & 1;
        #pragma unroll
        for (int ks = 0; ks < 2; ks++) {
            uint32_t a[4][4], bb[4][2];
            #pragma unroll
            for (int mf = 0; mf < 4; mf++) {
                int row = warp_m + mf * 16 + g;
                a[mf][0] = As[s][row    ][ks * 8 + tg];
                a[mf][1] = As[s][row + 8][ks * 8 + tg];
                a[mf][2] = As[s][row    ][ks * 8 + tg + 4];
                a[mf][3] = As[s][row + 8][ks * 8 + tg + 4];
            }
            #pragma unroll
            for (int nf = 0; nf < 4; nf++) {
                bb[nf][0] = Bs[s][ks * 8 + tg    ][warp_n + nf * 8 + g];
                bb[nf][1] = Bs[s][ks * 8 + tg + 4][warp_n + nf * 8 + g];
            }
            #pragma unroll
            for (int mf = 0; mf < 4; mf++)
                #pragma unroll
                for (int nf = 0; nf < 4; nf++)
                    mma_tf32(acc[mf][nf], a[mf], bb[nf]);
        }
        if (t < 15) STORE((t + 1) & 1);
        __syncthreads();
    }

    if (m0 < HID) {
        // ---- q: softmax over d (warp's 64 m-rows = one full head) ----
        #pragma unroll
        for (int nf = 0; nf < 4; nf++) {
            #pragma unroll
            for (int bc = 0; bc < 2; bc++) {
                float s = 0.f;
                #pragma unroll
                for (int mf = 0; mf < 4; mf++) {
                    float e0 = __expf(acc[mf][nf][bc]);
                    float e1 = __expf(acc[mf][nf][2 + bc]);
                    acc[mf][nf][bc]     = e0;
                    acc[mf][nf][2 + bc] = e1;
                    s += e0 + e1;
                }
                s += __shfl_xor_sync(0xffffffffu, s, 4);
                s += __shfl_xor_sync(0xffffffffu, s, 8);
                s += __shfl_xor_sync(0xffffffffu, s, 16);
                float sc = 0.125f / s;            // SCALE folded
                #pragma unroll
                for (int mf = 0; mf < 4; mf++) {
                    // preround to tf32 so gemm_out_ln can cp.async raw bits
                    acc[mf][nf][bc]     = __uint_as_float(f2tf32(acc[mf][nf][bc]     * sc));
                    acc[mf][nf][2 + bc] = __uint_as_float(f2tf32(acc[mf][nf][2 + bc] * sc));
                }
            }
        }
        float* op = g_qexp + (size_t)b * HID * HW;
        #pragma unroll
        for (int mf = 0; mf < 4; mf++) {
            int m = m0 + warp_m + mf * 16 + g;
            #pragma unroll
            for (int nf = 0; nf < 4; nf++) {
                int t = n0 + warp_n + nf * 8 + tg * 2;
                *(float2*)(op + (size_t)m * HW + t) =
                    make_float2(acc[mf][nf][0], acc[mf][nf][1]);
                *(float2*)(op + (size_t)(m + 8) * HW + t) =
                    make_float2(acc[mf][nf][2], acc[mf][nf][3]);
            }
        }
        return;
    }

    bool is_k = (m0 < 2 * HID);
    if (is_k) {
        #pragma unroll
        for (int mf = 0; mf < 4; mf++)
            #pragma unroll
            for (int nf = 0; nf < 4; nf++)
                #pragma unroll
                for (int i = 0; i < 4; i++)
                    acc[mf][nf][i] = __expf(acc[mf][nf][i]);

        #pragma unroll
        for (int mf = 0; mf < 4; mf++) {
            #pragma unroll
            for (int half = 0; half < 2; half++) {
                float s = 0.f;
                #pragma unroll
                for (int nf = 0; nf < 4; nf++) {
                    #pragma unroll
                    for (int bc = 0; bc < 2; bc++) {
                        int n = warp_n + nf * 8 + tg * 2 + bc;
                        float v = acc[mf][nf][half * 2 + bc];
                        s += (n0 + n < NTOK) ? v : 0.f;
                    }
                }
                s += __shfl_xor_sync(0xffffffffu, s, 1);
                s += __shfl_xor_sync(0xffffffffu, s, 2);
                if (tg == 0)
                    psum[wid >> 1][warp_m + mf * 16 + g + half * 8] = s;
            }
        }
        __syncthreads();
        if (tid < 128) {
            float s = psum[0][tid] + psum[1][tid] + psum[2][tid] + psum[3][tid];
            g_ksump[(size_t)blockIdx.x * (B * HID) + b * HID + (m0 - HID) + tid] = s;
        }
    }

    // ---- store k (ek) / v rows ----
    float* outp = g_qkv + (size_t)b * H3 * NTOK;
    #pragma unroll
    for (int mf = 0; mf < 4; mf++) {
        #pragma unroll
        for (int nf = 0; nf < 4; nf++) {
            int n = n0 + warp_n + nf * 8 + tg * 2;
            if (n < NTOK) {
                int m = m0 + warp_m + mf * 16 + g;
                *(float2*)(outp + (size_t)m * NTOK + n) =
                    make_float2(acc[mf][nf][0], acc[mf][nf][1]);
                *(float2*)(outp + (size_t)(m + 8) * NTOK + n) =
                    make_float2(acc[mf][nf][2], acc[mf][nf][3]);
            }
        }
    }
}

// =====================================================================
// K2: reduce per-tile k sums -> g_kinv = 1/total   (8192 rows, 33 tiles)
// =====================================================================
__global__ __launch_bounds__(256) void k_stats_reduce()
{
    int row = blockIdx.x * 256 + threadIdx.x;     // 0..8191
    float s = 0.f;
    #pragma unroll
    for (int nt = 0; nt < NTILES; nt++)
        s += g_ksump[(size_t)nt * (B * HID) + row];
    g_kinv[row] = 1.f / s;
}

// =====================================================================
// K3: partial ctxT[e][d] = sum_n v[e,n] * ek[d,n] over a 320-token chunk
// =====================================================================
__global__ __launch_bounds__(256) void k_context_p()
{
    __shared__ uint32_t Ks[64][68];       // ek[d][nt]  (B operand, n=d)
    __shared__ uint32_t Vs[64][68];       // v[e][nt]   (A operand, m=e)

    int ch = blockIdx.x;
    int h  = blockIdx.y;
    int b  = blockIdx.z;
    int bh = b * NHEADS + h;
    const float* kp = g_qkv + ((size_t)b * H3 + HID     + h * DH) * NTOK;
    const float* vp = g_qkv + ((size_t)b * H3 + 2 * HID + h * DH) * NTOK;

    int tid = threadIdx.x;
    int lane = tid & 31, wid = tid >> 5;
    int g = lane >> 2, tg = lane & 3;
    int we = (wid & 1) * 32;
    int wd = (wid >> 1) * 16;

    float acc[2][2][4];
    #pragma unroll
    for (int mf = 0; mf < 2; mf++)
        #pragma unroll
        for (int nf = 0; nf < 2; nf++)
            #pragma unroll
            for (int i = 0; i < 4; i++) acc[mf][nf][i] = 0.f;

    for (int tile = 0; tile < CHTOK / 64; tile++) {
        int n0 = ch * CHTOK + tile * 64;
        __syncthreads();
        #pragma unroll
        for (int r = 0; r < 4; r++) {
            int f = tid + r * 256;
            int row = f >> 4, c4 = (f & 15) * 4;
            float4 kv = *(const float4*)(kp + (size_t)row * NTOK + n0 + c4);
            Ks[row][c4 + 0] = f2tf32(kv.x);
            Ks[row][c4 + 1] = f2tf32(kv.y);
            Ks[row][c4 + 2] = f2tf32(kv.z);
            Ks[row][c4 + 3] = f2tf32(kv.w);
            float4 vv = *(const float4*)(vp + (size_t)row * NTOK + n0 + c4);
            Vs[row][c4 + 0] = f2tf32(vv.x);
            Vs[row][c4 + 1] = f2tf32(vv.y);
            Vs[row][c4 + 2] = f2tf32(vv.z);
            Vs[row][c4 + 3] = f2tf32(vv.w);
        }
        __syncthreads();
        #pragma unroll
        for (int ks = 0; ks < 8; ks++) {
            uint32_t a[2][4], bb[2][2];
            #pragma unroll
            for (int mf = 0; mf < 2; mf++) {
                int row = we + mf * 16 + g;
                a[mf][0] = Vs[row    ][ks * 8 + tg];
                a[mf][1] = Vs[row + 8][ks * 8 + tg];
                a[mf][2] = Vs[row    ][ks * 8 + tg + 4];
                a[mf][3] = Vs[row + 8][ks * 8 + tg + 4];
            }
            #pragma unroll
            for (int nf = 0; nf < 2; nf++) {
                bb[nf][0] = Ks[wd + nf * 8 + g][ks * 8 + tg];
                bb[nf][1] = Ks[wd + nf * 8 + g][ks * 8 + tg + 4];
            }
            #pragma unroll
            for (int mf = 0; mf < 2; mf++)
                #pragma unroll
                for (int nf = 0; nf < 2; nf++)
                    mma_tf32(acc[mf][nf], a[mf], bb[nf]);
        }
    }

    float* cp = g_ctxp + ((size_t)ch * B * NHEADS + bh) * DH * DH;
    #pragma unroll
    for (int mf = 0; mf < 2; mf++) {
        int e = we + mf * 16 + g;
        #pragma unroll
        for (int nf = 0; nf < 2; nf++) {
            int d = wd + nf * 8 + tg * 2;
            *(float2*)(cp + (size_t)e * DH + d)       = make_float2(acc[mf][nf][0], acc[mf][nf][1]);
            *(float2*)(cp + (size_t)(e + 8) * DH + d) = make_float2(acc[mf][nf][2], acc[mf][nf][3]);
        }
    }
}

// =====================================================================
// K4: reduce 13 partial context chunks + apply 1/sum column scale
// =====================================================================
__global__ __launch_bounds__(256) void ctx_reduce()
{
    int idx = (blockIdx.x * 256 + threadIdx.x) * 4;    // 512 blocks covers 524288
    float4 s = *(const float4*)(g_ctxp + idx);
    #pragma unroll
    for (int ch = 1; ch < NCHUNK; ch++) {
        float4 v = *(const float4*)(g_ctxp + (size_t)ch * (B * NHEADS * DH * DH) + idx);
        s.x += v.x; s.y += v.y; s.z += v.z; s.w += v.w;
    }
    int bh = idx >> 12;          // 4096 elements per bh
    int d  = idx & 63;
    float4 inv = *(const float4*)(g_kinv + bh * 64 + d);
    s.x *= inv.x; s.y *= inv.y; s.z *= inv.z; s.w *= inv.w;
    *(float4*)(g_ctxT + idx) = s;
}

// =====================================================================
// K5: fold context into output weights (tf32-prerounded store):
//   Wc[b][o][h*64+d] = sum_e Wout[o][h*64+e] * ctxT[b,h][e][d]
// =====================================================================
__global__ __launch_bounds__(256) void ctx_fold(const float* __restrict__ Wout)
{
    __shared__ float ctx_s[64][68];      // [e][d]
    __shared__ float w_s[64][68];        // [o_local][e]

    int o0 = blockIdx.x * 64;
    int h  = blockIdx.y;
    int b  = blockIdx.z;
    int bh = b * NHEADS + h;
    int tid = threadIdx.x;

    const float* cp = g_ctxT + (size_t)bh * DH * DH;
    #pragma unroll
    for (int r = 0; r < 4; r++) {
        int f = tid + r * 256;
        int row = f >> 4, c4 = (f & 15) * 4;
        *(float4*)&ctx_s[row][c4] = *(const float4*)(cp + (size_t)row * DH + c4);
        *(float4*)&w_s[row][c4]   = *(const float4*)(Wout + (size_t)(o0 + row) * HID + h * DH + c4);
    }
    __syncthreads();

    int og = tid >> 6;
    int d  = tid & 63;
    float acc[16];
    #pragma unroll
    for (int i = 0; i < 16; i++) acc[i] = 0.f;
    #pragma unroll 4
    for (int e = 0; e < 64; e++) {
        float c = ctx_s[e][d];
        #pragma unroll
        for (int i = 0; i < 16; i++)
            acc[i] = fmaf(w_s[og * 16 + i][e], c, acc[i]);
    }
    float* wcp = g_wc + ((size_t)b * C) * HID;
    #pragma unroll
    for (int i = 0; i < 16; i++)
        wcp[(size_t)(o0 + og * 16 + i) * HID + h * DH + d] =
            __uint_as_float(f2tf32(acc[i]));
}

// =====================================================================
// K6: y = LN( Wc_b @ qexp + bias )   (M=256 per block, N=128, K=512)
// cp.async 2-stage pipeline; operands are tf32-prerounded raw bits.
// =====================================================================
#define OUT_A_BYTES (256 * 36 * 4)                  // 36864
#define OUT_STAGE   (OUT_A_BYTES + 32 * 136 * 4)    // 36864 + 17408 = 54272
#define OUT_SMEM    (2 * OUT_STAGE + 8192)          // 116736

__global__ __launch_bounds__(256) void gemm_out_ln(
    const float* __restrict__ bias, const float* __restrict__ lng,
    const float* __restrict__ lnb, float* __restrict__ y)
{
    extern __shared__ char dyn[];
    float* swsum = (float*)(dyn + 2 * OUT_STAGE);            // 4x128
    float* swsq  = (float*)(dyn + 2 * OUT_STAGE + 2048);     // 4x128
    float* sbias = (float*)(dyn + 2 * OUT_STAGE + 4096);     // 256
    float* slg   = (float*)(dyn + 2 * OUT_STAGE + 5120);     // 256
    float* slb   = (float*)(dyn + 2 * OUT_STAGE + 6144);     // 256
    float* smean = (float*)(dyn + 2 * OUT_STAGE + 7168);     // 128
    float* srstd = (float*)(dyn + 2 * OUT_STAGE + 7680);     // 128

    int t0 = blockIdx.x * 128;
    int b  = blockIdx.z;
    int tid  = threadIdx.x;
    int lane = tid & 31, wid = tid >> 5;
    int g = lane >> 2, tg = lane & 3;
    int wm = wid & 3;
    int wn = wid >> 2;

    sbias[tid] = bias[tid];
    slg[tid]   = lng[tid];
    slb[tid]   = lnb[tid];

    const float* Ap = g_wc + (size_t)b * C * HID;
    const float* Bp = g_qexp + (size_t)b * HID * HW;
    uint32_t sbase = (uint32_t)__cvta_generic_to_shared(dyn);

    auto PREFETCH = [&](int t) {        // tile t -> buffer t&1
        int k0 = t * 32;
        uint32_t abase = sbase + (t & 1) * OUT_STAGE;
        uint32_t bbase = abase + OUT_A_BYTES;
        #pragma unroll
        for (int r = 0; r < 8; r++) {
            int idx = tid + r * 256;     // 2048 16B chunks for A
            int row = idx >> 3, kc = (idx & 7) * 4;
            cp16(abase + (row * 36 + kc) * 4, Ap + (size_t)row * HID + k0 + kc);
        }
        #pragma unroll
        for (int r = 0; r < 4; r++) {
            int idx = tid + r * 256;     // 1024 16B chunks for B
            int row = idx >> 5, nc = (idx & 31) * 4;
            cp16(bbase + (row * 136 + nc) * 4, Bp + (size_t)(k0 + row) * HW + t0 + nc);
        }
        CP_COMMIT();
    };

    float acc[4][8][4];
    #pragma unroll
    for (int mf = 0; mf < 4; mf++)
        #pragma unroll
        for (int nf = 0; nf < 8; nf++)
            #pragma unroll
            for (int i = 0; i < 4; i++) acc[mf][nf][i] = 0.f;

    PREFETCH(0);

    #pragma unroll 2
    for (int t = 0; t < 16; t++) {                  // 16 k-tiles of 32
        if (t + 1 < 16) {
            PREFETCH(t + 1);
            asm volatile("cp.async.wait_group 1;\n" ::: "memory");
        } else {
            asm volatile("cp.async.wait_group 0;\n" ::: "memory");
        }
        __syncthreads();

        uint32_t (*As)[36]  = (uint32_t(*)[36])(dyn + (t & 1) * OUT_STAGE);
        uint32_t (*Bs)[136] = (uint32_t(*)[136])(dyn + (t & 1) * OUT_STAGE + OUT_A_BYTES);
        #pragma unroll
        for (int ks = 0; ks < 4; ks++) {
            uint32_t a[4][4], bb[8][2];
            #pragma unroll
            for (int mf = 0; mf < 4; mf++) {
                int row = wm * 64 + mf * 16 + g;
                a[mf][0] = As[row    ][ks * 8 + tg];
                a[mf][1] = As[row + 8][ks * 8 + tg];
                a[mf][2] = As[row    ][ks * 8 + tg + 4];
                a[mf][3] = As[row + 8][ks * 8 + tg + 4];
            }
            #pragma unroll
            for (int nf = 0; nf < 8; nf++) {
                bb[nf][0] = Bs[ks * 8 + tg    ][wn * 64 + nf * 8 + g];
                bb[nf][1] = Bs[ks * 8 + tg + 4][wn * 64 + nf * 8 + g];
            }
            #pragma unroll
            for (int mf = 0; mf < 4; mf++)
                #pragma unroll
                for (int nf = 0; nf < 8; nf++)
                    mma_tf32(acc[mf][nf], a[mf], bb[nf]);
        }
        __syncthreads();
    }

    // ---- LayerNorm over o=256 per token ----
    float psum[16], psq[16];
    #pragma unroll
    for (int j = 0; j < 16; j++) { psum[j] = 0.f; psq[j] = 0.f; }
    #pragma unroll
    for (int mf = 0; mf < 4; mf++) {
        int o0r = wm * 64 + mf * 16 + g;
        float b0 = sbias[o0r], b1 = sbias[o0r + 8];
        #pragma unroll
        for (int nf = 0; nf < 8; nf++) {
            #pragma unroll
            for (int bc = 0; bc < 2; bc++) {
                float v0 = acc[mf][nf][bc]     + b0;
                float v1 = acc[mf][nf][2 + bc] + b1;
                psum[nf * 2 + bc] += v0 + v1;
                psq[nf * 2 + bc]  += v0 * v0 + v1 * v1;
            }
        }
    }
    #pragma unroll
    for (int o = 4; o <= 16; o <<= 1) {
        #pragma unroll
        for (int j = 0; j < 16; j++) {
            psum[j] += __shfl_xor_sync(0xffffffffu, psum[j], o);
            psq[j]  += __shfl_xor_sync(0xffffffffu, psq[j], o);
        }
    }
    __syncthreads();
    if (g == 0) {
        #pragma unroll
        for (int nf = 0; nf < 8; nf++)
            #pragma unroll
            for (int bc = 0; bc < 2; bc++) {
                int tl = wn * 64 + nf * 8 + tg * 2 + bc;
                swsum[wm * 128 + tl] = psum[nf * 2 + bc];
                swsq[wm * 128 + tl]  = psq[nf * 2 + bc];
            }
    }
    __syncthreads();
    if (tid < 128) {
        float s  = swsum[tid] + swsum[128 + tid] + swsum[256 + tid] + swsum[384 + tid];
        float sq = swsq[tid]  + swsq[128 + tid]  + swsq[256 + tid]  + swsq[384 + tid];
        float mean = s * (1.f / 256.f);
        float var  = sq * (1.f / 256.f) - mean * mean;
        smean[tid] = mean;
        srstd[tid] = rsqrtf(var + 1e-5f);
    }
    __syncthreads();

    float* outp = y + (size_t)b * C * HW;
    #pragma unroll
    for (int mf = 0; mf < 4; mf++) {
        int o0r = wm * 64 + mf * 16 + g;
        float b0 = sbias[o0r],   g0 = slg[o0r],   be0 = slb[o0r];
        float b1 = sbias[o0r+8], g1 = slg[o0r+8], be1 = slb[o0r+8];
        #pragma unroll
        for (int nf = 0; nf < 8; nf++) {
            int tl = wn * 64 + nf * 8 + tg * 2;
            float m0 = smean[tl], m1 = smean[tl + 1];
            float r0 = srstd[tl], r1 = srstd[tl + 1];
            float2 v0, v1;
            v0.x = (acc[mf][nf][0] + b0 - m0) * r0 * g0 + be0;
            v0.y = (acc[mf][nf][1] + b0 - m1) * r1 * g0 + be0;
            v1.x = (acc[mf][nf][2] + b1 - m0) * r0 * g1 + be1;
            v1.y = (acc[mf][nf][3] + b1 - m1) * r1 * g1 + be1;
            *(float2*)(outp + (size_t)o0r * HW + t0 + tl)       = v0;
            *(float2*)(outp + (size_t)(o0r + 8) * HW + t0 + tl) = v1;
        }
    }
}

// =====================================================================
extern "C" void kernel_launch(void* const* d_in, const int* in_sizes, int n_in,
                              void* d_out, int out_size)
{
    const float* x    = (const float*)d_in[0];
    const float* mem  = (const float*)d_in[1];
    const float* Wqkv = (const float*)d_in[2];
    const float* Wout = (const float*)d_in[3];
    const float* bout = (const float*)d_in[4];
    const float* lng  = (const float*)d_in[5];
    const float* lnb  = (const float*)d_in[6];
    float* y = (float*)d_out;

    cudaFuncSetAttribute(gemm_out_ln, cudaFuncAttributeMaxDynamicSharedMemorySize, OUT_SMEM);

    gemm_qkv<<<dim3(NTILES, 12, B), 256>>>(x, mem, Wqkv);
    k_stats_reduce<<<32, 256>>>();
    k_context_p<<<dim3(NCHUNK, NHEADS, B), 256>>>();
    ctx_reduce<<<512, 256>>>();
    ctx_fold<<<dim3(4, NHEADS, B), 256>>>(Wout);
    gemm_out_ln<<<dim3(HW / 128, 1, B), 256, OUT_SMEM>>>(bout, lng, lnb, y);
}

// round 15
// speedup vs baseline: 1.1086x; 1.1086x over previous
#include <cuda_runtime.h>
#include <math.h>
#include <stdint.h>

#define B      16
#define C      256
#define HW     4096
#define MEM    64
#define NTOK   4160
#define H3     1536
#define HID    512
#define NHEADS 8
#define DH     64
#define NTILES 33      // n-tiles (also ctx partial chunks now)

// -------- scratch (device globals, fully overwritten every launch) --------
__device__ float g_ksump[NTILES * B * HID];        // per-n-tile partial sums of exp(k)
__device__ float g_kinv[B * HID];                  // 1 / total sum
__device__ float g_qexp[(size_t)B * HID * HW];     // softmaxed+scaled q (tf32-prerounded)
__device__ float g_ctxp[(size_t)NTILES * B * NHEADS * DH * DH];  // partial ctxT [nt][bh][e][d]
__device__ float g_ctxT[B * NHEADS * DH * DH];     // ctxT [bh][e][d], inv applied
__device__ float g_wc[(size_t)B * C * HID];        // folded weights (tf32-prerounded)

// ---------------- tf32 mma helpers ----------------
__device__ __forceinline__ uint32_t f2tf32(float f) {
    uint32_t r;
    asm("cvt.rna.tf32.f32 %0, %1;" : "=r"(r) : "f"(f));
    return r;
}

__device__ __forceinline__ void mma_tf32(float* d, const uint32_t* a, const uint32_t* b) {
    asm volatile(
        "mma.sync.aligned.m16n8k8.row.col.f32.tf32.tf32.f32 "
        "{%0,%1,%2,%3}, {%4,%5,%6,%7}, {%8,%9}, {%0,%1,%2,%3};\n"
        : "+f"(d[0]), "+f"(d[1]), "+f"(d[2]), "+f"(d[3])
        : "r"(a[0]), "r"(a[1]), "r"(a[2]), "r"(a[3]), "r"(b[0]), "r"(b[1]));
}

__device__ __forceinline__ void cp16(uint32_t dst, const void* src) {
    asm volatile("cp.async.cg.shared.global [%0], [%1], 16;\n" :: "r"(dst), "l"(src));
}
#define CP_COMMIT() asm volatile("cp.async.commit_group;\n")

// =====================================================================
// K1: fused qkv GEMM + attention front-end (tf32 MMA, R10 mainloop).
//  y<4 : q blocks   -> in-register softmax over d, write g_qexp (tf32 bits)
//  y>=4: head blocks (k-head h rows 0..63, v-head h rows 64..127)
//        -> exp(k) + per-row partial sums -> g_ksump
//        -> in-block 64x64x128 context partial via smem -> g_ctxp
// dyn smem: union { mainloop As[128][36]+Bs[32][136] (35840B),
//                   ctx Ks[64][132]+Vs[64][132] (67584B) } = 67584B, occ=2
// =====================================================================
#define QKV_DYN 67584

__global__ __launch_bounds__(256, 2) void gemm_qkv(
    const float* __restrict__ x, const float* __restrict__ mem,
    const float* __restrict__ W)
{
    extern __shared__ char dyn[];
    uint32_t (*As)[36]  = (uint32_t(*)[36])dyn;
    uint32_t (*Bs)[136] = (uint32_t(*)[136])(dyn + 18432);
    uint32_t (*Ks)[132] = (uint32_t(*)[132])dyn;             // alias (post-mainloop)
    uint32_t (*Vs)[132] = (uint32_t(*)[132])(dyn + 33792);
    __shared__ float psum[4][64];

    int b  = blockIdx.z;
    int y  = blockIdx.y;
    int nt = blockIdx.x;
    int n0 = nt * 128;
    bool is_q = (y < 4);
    int h = y - 4;                       // valid for head blocks
    int tid  = threadIdx.x;
    int lane = tid & 31, wid = tid >> 5;
    int warp_m = (wid & 1) * 64;
    int warp_n = (wid >> 1) * 32;
    int g = lane >> 2, tg = lane & 3;

    const float* src;
    int stride, col0, ncols;
    if (n0 < HW) { src = x + (size_t)b * C * HW; stride = HW;  col0 = n0; ncols = 128; }
    else {
        if (is_q) return;                // q not needed at memory tokens
        src = mem; stride = MEM; col0 = 0; ncols = MEM;
    }

    float acc[4][4][4];
    #pragma unroll
    for (int mf = 0; mf < 4; mf++)
        #pragma unroll
        for (int nf = 0; nf < 4; nf++)
            #pragma unroll
            for (int i = 0; i < 4; i++) acc[mf][nf][i] = 0.f;

    for (int k0 = 0; k0 < C; k0 += 32) {
        __syncthreads();
        #pragma unroll
        for (int r = 0; r < 4; r++) {
            int idx = tid + r * 256;
            int row = idx >> 3;
            int kc  = (idx & 7) * 4;
            int wrow;
            if (is_q) wrow = y * 128 + row;
            else      wrow = (row < 64) ? (HID + h * DH + row)
                                        : (2 * HID + h * DH + row - 64);
            float4 v = *(const float4*)(W + (size_t)wrow * C + k0 + kc);
            As[row][kc + 0] = f2tf32(v.x);
            As[row][kc + 1] = f2tf32(v.y);
            As[row][kc + 2] = f2tf32(v.z);
            As[row][kc + 3] = f2tf32(v.w);
        }
        #pragma unroll
        for (int r = 0; r < 4; r++) {
            int idx = tid + r * 256;
            int row = idx >> 5;
            int nc  = (idx & 31) * 4;
            float4 v;
            if (nc + 3 < ncols)
                v = *(const float4*)(src + (size_t)(k0 + row) * stride + col0 + nc);
            else
                v = make_float4(0.f, 0.f, 0.f, 0.f);
            Bs[row][nc + 0] = f2tf32(v.x);
            Bs[row][nc + 1] = f2tf32(v.y);
            Bs[row][nc + 2] = f2tf32(v.z);
            Bs[row][nc + 3] = f2tf32(v.w);
        }
        __syncthreads();
        #pragma unroll
        for (int ks = 0; ks < 4; ks++) {
            uint32_t a[4][4], bb[4][2];
            #pragma unroll
            for (int mf = 0; mf < 4; mf++) {
                int row = warp_m + mf * 16 + g;
                a[mf][0] = As[row    ][ks * 8 + tg];
                a[mf][1] = As[row + 8][ks * 8 + tg];
                a[mf][2] = As[row    ][ks * 8 + tg + 4];
                a[mf][3] = As[row + 8][ks * 8 + tg + 4];
            }
            #pragma unroll
            for (int nf = 0; nf < 4; nf++) {
                bb[nf][0] = Bs[ks * 8 + tg    ][warp_n + nf * 8 + g];
                bb[nf][1] = Bs[ks * 8 + tg + 4][warp_n + nf * 8 + g];
            }
            #pragma unroll
            for (int mf = 0; mf < 4; mf++)
                #pragma unroll
                for (int nf = 0; nf < 4; nf++)
                    mma_tf32(acc[mf][nf], a[mf], bb[nf]);
        }
    }
    __syncthreads();     // mainloop smem dead; safe to alias as Ks/Vs below

    if (is_q) {
        // ---- q: softmax over d (warp's 64 m-rows = one full head) ----
        #pragma unroll
        for (int nf = 0; nf < 4; nf++) {
            #pragma unroll
            for (int bc = 0; bc < 2; bc++) {
                float s = 0.f;
                #pragma unroll
                for (int mf = 0; mf < 4; mf++) {
                    float e0 = __expf(acc[mf][nf][bc]);
                    float e1 = __expf(acc[mf][nf][2 + bc]);
                    acc[mf][nf][bc]     = e0;
                    acc[mf][nf][2 + bc] = e1;
                    s += e0 + e1;
                }
                s += __shfl_xor_sync(0xffffffffu, s, 4);
                s += __shfl_xor_sync(0xffffffffu, s, 8);
                s += __shfl_xor_sync(0xffffffffu, s, 16);
                float sc = 0.125f / s;            // SCALE folded
                #pragma unroll
                for (int mf = 0; mf < 4; mf++) {
                    acc[mf][nf][bc]     = __uint_as_float(f2tf32(acc[mf][nf][bc]     * sc));
                    acc[mf][nf][2 + bc] = __uint_as_float(f2tf32(acc[mf][nf][2 + bc] * sc));
                }
            }
        }
        float* op = g_qexp + (size_t)b * HID * HW;
        #pragma unroll
        for (int mf = 0; mf < 4; mf++) {
            int m = y * 128 + warp_m + mf * 16 + g;
            #pragma unroll
            for (int nf = 0; nf < 4; nf++) {
                int t = n0 + warp_n + nf * 8 + tg * 2;
                *(float2*)(op + (size_t)m * HW + t) =
                    make_float2(acc[mf][nf][0], acc[mf][nf][1]);
                *(float2*)(op + (size_t)(m + 8) * HW + t) =
                    make_float2(acc[mf][nf][2], acc[mf][nf][3]);
            }
        }
        return;
    }

    // ================= head block epilogue =================
    bool is_kw = ((wid & 1) == 0);       // warp holds k rows (0..63) else v rows
    if (is_kw) {
        // exp in place + per-row partial sums over valid tokens
        #pragma unroll
        for (int mf = 0; mf < 4; mf++)
            #pragma unroll
            for (int nf = 0; nf < 4; nf++)
                #pragma unroll
                for (int i = 0; i < 4; i++)
                    acc[mf][nf][i] = __expf(acc[mf][nf][i]);

        #pragma unroll
        for (int mf = 0; mf < 4; mf++) {
            #pragma unroll
            for (int half = 0; half < 2; half++) {
                float s = 0.f;
                #pragma unroll
                for (int nf = 0; nf < 4; nf++) {
                    #pragma unroll
                    for (int bc = 0; bc < 2; bc++) {
                        int n = warp_n + nf * 8 + tg * 2 + bc;
                        float v = acc[mf][nf][half * 2 + bc];
                        s += (n0 + n < NTOK) ? v : 0.f;
                    }
                }
                s += __shfl_xor_sync(0xffffffffu, s, 1);
                s += __shfl_xor_sync(0xffffffffu, s, 2);
                if (tg == 0)
                    psum[wid >> 1][mf * 16 + g + half * 8] = s;
            }
        }
    }

    // write ek / v tiles to smem (tf32 bits), rows local 0..63, cols 0..127
    {
        uint32_t (*T)[132] = is_kw ? Ks : Vs;
        #pragma unroll
        for (int mf = 0; mf < 4; mf++) {
            int r = mf * 16 + g;
            #pragma unroll
            for (int nf = 0; nf < 4; nf++) {
                int ccol = warp_n + nf * 8 + tg * 2;
                T[r][ccol]         = f2tf32(acc[mf][nf][0]);
                T[r][ccol + 1]     = f2tf32(acc[mf][nf][1]);
                T[r + 8][ccol]     = f2tf32(acc[mf][nf][2]);
                T[r + 8][ccol + 1] = f2tf32(acc[mf][nf][3]);
            }
        }
    }
    __syncthreads();

    if (tid < 64) {
        float s = psum[0][tid] + psum[1][tid] + psum[2][tid] + psum[3][tid];
        g_ksump[(size_t)nt * (B * HID) + b * HID + h * DH + tid] = s;
    }

    // ---- in-block context partial: D[e][d] = sum_n Vs[e,n] * Ks[d,n] ----
    int we = (wid & 1) * 32;
    int wd = (wid >> 1) * 16;
    float acc2[2][2][4];
    #pragma unroll
    for (int mf = 0; mf < 2; mf++)
        #pragma unroll
        for (int nf = 0; nf < 2; nf++)
            #pragma unroll
            for (int i = 0; i < 4; i++) acc2[mf][nf][i] = 0.f;

    #pragma unroll
    for (int ks = 0; ks < 16; ks++) {
        uint32_t a[2][4], bb[2][2];
        #pragma unroll
        for (int mf = 0; mf < 2; mf++) {
            int row = we + mf * 16 + g;
            a[mf][0] = Vs[row    ][ks * 8 + tg];
            a[mf][1] = Vs[row + 8][ks * 8 + tg];
            a[mf][2] = Vs[row    ][ks * 8 + tg + 4];
            a[mf][3] = Vs[row + 8][ks * 8 + tg + 4];
        }
        #pragma unroll
        for (int nf = 0; nf < 2; nf++) {
            bb[nf][0] = Ks[wd + nf * 8 + g][ks * 8 + tg];
            bb[nf][1] = Ks[wd + nf * 8 + g][ks * 8 + tg + 4];
        }
        #pragma unroll
        for (int mf = 0; mf < 2; mf++)
            #pragma unroll
            for (int nf = 0; nf < 2; nf++)
                mma_tf32(acc2[mf][nf], a[mf], bb[nf]);
    }

    float* cp = g_ctxp + ((size_t)nt * (B * NHEADS) + b * NHEADS + h) * (DH * DH);
    #pragma unroll
    for (int mf = 0; mf < 2; mf++) {
        int e = we + mf * 16 + g;
        #pragma unroll
        for (int nf = 0; nf < 2; nf++) {
            int d = wd + nf * 8 + tg * 2;
            *(float2*)(cp + (size_t)e * DH + d)       = make_float2(acc2[mf][nf][0], acc2[mf][nf][1]);
            *(float2*)(cp + (size_t)(e + 8) * DH + d) = make_float2(acc2[mf][nf][2], acc2[mf][nf][3]);
        }
    }
}

// =====================================================================
// K2: reduce per-tile k sums -> g_kinv = 1/total   (8192 rows, 33 tiles)
// =====================================================================
__global__ __launch_bounds__(256) void k_stats_reduce()
{
    int row = blockIdx.x * 256 + threadIdx.x;     // 0..8191
    float s = 0.f;
    #pragma unroll
    for (int nt = 0; nt < NTILES; nt++)
        s += g_ksump[(size_t)nt * (B * HID) + row];
    g_kinv[row] = 1.f / s;
}

// =====================================================================
// K3: reduce 33 partial context chunks + apply 1/sum column scale
// =====================================================================
__global__ __launch_bounds__(256) void ctx_reduce()
{
    int idx = (blockIdx.x * 256 + threadIdx.x) * 4;    // 512 blocks covers 524288
    float4 s = *(const float4*)(g_ctxp + idx);
    #pragma unroll
    for (int ch = 1; ch < NTILES; ch++) {
        float4 v = *(const float4*)(g_ctxp + (size_t)ch * (B * NHEADS * DH * DH) + idx);
        s.x += v.x; s.y += v.y; s.z += v.z; s.w += v.w;
    }
    int bh = idx >> 12;          // 4096 elements per bh
    int d  = idx & 63;
    float4 inv = *(const float4*)(g_kinv + bh * 64 + d);
    s.x *= inv.x; s.y *= inv.y; s.z *= inv.z; s.w *= inv.w;
    *(float4*)(g_ctxT + idx) = s;
}

// =====================================================================
// K4: fold context into output weights (tf32-prerounded store):
//   Wc[b][o][h*64+d] = sum_e Wout[o][h*64+e] * ctxT[b,h][e][d]
// =====================================================================
__global__ __launch_bounds__(256) void ctx_fold(const float* __restrict__ Wout)
{
    __shared__ float ctx_s[64][68];      // [e][d]
    __shared__ float w_s[64][68];        // [o_local][e]

    int o0 = blockIdx.x * 64;
    int h  = blockIdx.y;
    int b  = blockIdx.z;
    int bh = b * NHEADS + h;
    int tid = threadIdx.x;

    const float* cp = g_ctxT + (size_t)bh * DH * DH;
    #pragma unroll
    for (int r = 0; r < 4; r++) {
        int f = tid + r * 256;
        int row = f >> 4, c4 = (f & 15) * 4;
        *(float4*)&ctx_s[row][c4] = *(const float4*)(cp + (size_t)row * DH + c4);
        *(float4*)&w_s[row][c4]   = *(const float4*)(Wout + (size_t)(o0 + row) * HID + h * DH + c4);
    }
    __syncthreads();

    int og = tid >> 6;
    int d  = tid & 63;
    float acc[16];
    #pragma unroll
    for (int i = 0; i < 16; i++) acc[i] = 0.f;
    #pragma unroll 4
    for (int e = 0; e < 64; e++) {
        float c = ctx_s[e][d];
        #pragma unroll
        for (int i = 0; i < 16; i++)
            acc[i] = fmaf(w_s[og * 16 + i][e], c, acc[i]);
    }
    float* wcp = g_wc + ((size_t)b * C) * HID;
    #pragma unroll
    for (int i = 0; i < 16; i++)
        wcp[(size_t)(o0 + og * 16 + i) * HID + h * DH + d] =
            __uint_as_float(f2tf32(acc[i]));
}

// =====================================================================
// K5: y = LN( Wc_b @ qexp + bias )   (M=256 per block, N=128, K=512)
// cp.async 2-stage pipeline; operands are tf32-prerounded raw bits.
// =====================================================================
#define OUT_A_BYTES (256 * 36 * 4)                  // 36864
#define OUT_STAGE   (OUT_A_BYTES + 32 * 136 * 4)    // 36864 + 17408 = 54272
#define OUT_SMEM    (2 * OUT_STAGE + 8192)          // 116736

__global__ __launch_bounds__(256) void gemm_out_ln(
    const float* __restrict__ bias, const float* __restrict__ lng,
    const float* __restrict__ lnb, float* __restrict__ y)
{
    extern __shared__ char dyn[];
    float* swsum = (float*)(dyn + 2 * OUT_STAGE);            // 4x128
    float* swsq  = (float*)(dyn + 2 * OUT_STAGE + 2048);     // 4x128
    float* sbias = (float*)(dyn + 2 * OUT_STAGE + 4096);     // 256
    float* slg   = (float*)(dyn + 2 * OUT_STAGE + 5120);     // 256
    float* slb   = (float*)(dyn + 2 * OUT_STAGE + 6144);     // 256
    float* smean = (float*)(dyn + 2 * OUT_STAGE + 7168);     // 128
    float* srstd = (float*)(dyn + 2 * OUT_STAGE + 7680);     // 128

    int t0 = blockIdx.x * 128;
    int b  = blockIdx.z;
    int tid  = threadIdx.x;
    int lane = tid & 31, wid = tid >> 5;
    int g = lane >> 2, tg = lane & 3;
    int wm = wid & 3;
    int wn = wid >> 2;

    sbias[tid] = bias[tid];
    slg[tid]   = lng[tid];
    slb[tid]   = lnb[tid];

    const float* Ap = g_wc + (size_t)b * C * HID;
    const float* Bp = g_qexp + (size_t)b * HID * HW;
    uint32_t sbase = (uint32_t)__cvta_generic_to_shared(dyn);

    auto PREFETCH = [&](int t) {        // tile t -> buffer t&1
        int k0 = t * 32;
        uint32_t abase = sbase + (t & 1) * OUT_STAGE;
        uint32_t bbase = abase + OUT_A_BYTES;
        #pragma unroll
        for (int r = 0; r < 8; r++) {
            int idx = tid + r * 256;     // 2048 16B chunks for A
            int row = idx >> 3, kc = (idx & 7) * 4;
            cp16(abase + (row * 36 + kc) * 4, Ap + (size_t)row * HID + k0 + kc);
        }
        #pragma unroll
        for (int r = 0; r < 4; r++) {
            int idx = tid + r * 256;     // 1024 16B chunks for B
            int row = idx >> 5, nc = (idx & 31) * 4;
            cp16(bbase + (row * 136 + nc) * 4, Bp + (size_t)(k0 + row) * HW + t0 + nc);
        }
        CP_COMMIT();
    };

    float acc[4][8][4];
    #pragma unroll
    for (int mf = 0; mf < 4; mf++)
        #pragma unroll
        for (int nf = 0; nf < 8; nf++)
            #pragma unroll
            for (int i = 0; i < 4; i++) acc[mf][nf][i] = 0.f;

    PREFETCH(0);

    #pragma unroll 2
    for (int t = 0; t < 16; t++) {                  // 16 k-tiles of 32
        if (t + 1 < 16) {
            PREFETCH(t + 1);
            asm volatile("cp.async.wait_group 1;\n" ::: "memory");
        } else {
            asm volatile("cp.async.wait_group 0;\n" ::: "memory");
        }
        __syncthreads();

        uint32_t (*As)[36]  = (uint32_t(*)[36])(dyn + (t & 1) * OUT_STAGE);
        uint32_t (*Bs)[136] = (uint32_t(*)[136])(dyn + (t & 1) * OUT_STAGE + OUT_A_BYTES);
        #pragma unroll
        for (int ks = 0; ks < 4; ks++) {
            uint32_t a[4][4], bb[8][2];
            #pragma unroll
            for (int mf = 0; mf < 4; mf++) {
                int row = wm * 64 + mf * 16 + g;
                a[mf][0] = As[row    ][ks * 8 + tg];
                a[mf][1] = As[row + 8][ks * 8 + tg];
                a[mf][2] = As[row    ][ks * 8 + tg + 4];
                a[mf][3] = As[row + 8][ks * 8 + tg + 4];
            }
            #pragma unroll
            for (int nf = 0; nf < 8; nf++) {
                bb[nf][0] = Bs[ks * 8 + tg    ][wn * 64 + nf * 8 + g];
                bb[nf][1] = Bs[ks * 8 + tg + 4][wn * 64 + nf * 8 + g];
            }
            #pragma unroll
            for (int mf = 0; mf < 4; mf++)
                #pragma unroll
                for (int nf = 0; nf < 8; nf++)
                    mma_tf32(acc[mf][nf], a[mf], bb[nf]);
        }
        __syncthreads();
    }

    // ---- LayerNorm over o=256 per token ----
    float psum[16], psq[16];
    #pragma unroll
    for (int j = 0; j < 16; j++) { psum[j] = 0.f; psq[j] = 0.f; }
    #pragma unroll
    for (int mf = 0; mf < 4; mf++) {
        int o0r = wm * 64 + mf * 16 + g;
        float b0 = sbias[o0r], b1 = sbias[o0r + 8];
        #pragma unroll
        for (int nf = 0; nf < 8; nf++) {
            #pragma unroll
            for (int bc = 0; bc < 2; bc++) {
                float v0 = acc[mf][nf][bc]     + b0;
                float v1 = acc[mf][nf][2 + bc] + b1;
                psum[nf * 2 + bc] += v0 + v1;
                psq[nf * 2 + bc]  += v0 * v0 + v1 * v1;
            }
        }
    }
    #pragma unroll
    for (int o = 4; o <= 16; o <<= 1) {
        #pragma unroll
        for (int j = 0; j < 16; j++) {
            psum[j] += __shfl_xor_sync(0xffffffffu, psum[j], o);
            psq[j]  += __shfl_xor_sync(0xffffffffu, psq[j], o);
        }
    }
    __syncthreads();
    if (g == 0) {
        #pragma unroll
        for (int nf = 0; nf < 8; nf++)
            #pragma unroll
            for (int bc = 0; bc < 2; bc++) {
                int tl = wn * 64 + nf * 8 + tg * 2 + bc;
                swsum[wm * 128 + tl] = psum[nf * 2 + bc];
                swsq[wm * 128 + tl]  = psq[nf * 2 + bc];
            }
    }
    __syncthreads();
    if (tid < 128) {
        float s  = swsum[tid] + swsum[128 + tid] + swsum[256 + tid] + swsum[384 + tid];
        float sq = swsq[tid]  + swsq[128 + tid]  + swsq[256 + tid]  + swsq[384 + tid];
        float mean = s * (1.f / 256.f);
        float var  = sq * (1.f / 256.f) - mean * mean;
        smean[tid] = mean;
        srstd[tid] = rsqrtf(var + 1e-5f);
    }
    __syncthreads();

    float* outp = y + (size_t)b * C * HW;
    #pragma unroll
    for (int mf = 0; mf < 4; mf++) {
        int o0r = wm * 64 + mf * 16 + g;
        float b0 = sbias[o0r],   g0 = slg[o0r],   be0 = slb[o0r];
        float b1 = sbias[o0r+8], g1 = slg[o0r+8], be1 = slb[o0r+8];
        #pragma unroll
        for (int nf = 0; nf < 8; nf++) {
            int tl = wn * 64 + nf * 8 + tg * 2;
            float m0 = smean[tl], m1 = smean[tl + 1];
            float r0 = srstd[tl], r1 = srstd[tl + 1];
            float2 v0, v1;
            v0.x = (acc[mf][nf][0] + b0 - m0) * r0 * g0 + be0;
            v0.y = (acc[mf][nf][1] + b0 - m1) * r1 * g0 + be0;
            v1.x = (acc[mf][nf][2] + b1 - m0) * r0 * g1 + be1;
            v1.y = (acc[mf][nf][3] + b1 - m1) * r1 * g1 + be1;
            *(float2*)(outp + (size_t)o0r * HW + t0 + tl)       = v0;
            *(float2*)(outp + (size_t)(o0r + 8) * HW + t0 + tl) = v1;
        }
    }
}

// =====================================================================
extern "C" void kernel_launch(void* const* d_in, const int* in_sizes, int n_in,
                              void* d_out, int out_size)
{
    const float* x    = (const float*)d_in[0];
    const float* mem  = (const float*)d_in[1];
    const float* Wqkv = (const float*)d_in[2];
    const float* Wout = (const float*)d_in[3];
    const float* bout = (const float*)d_in[4];
    const float* lng  = (const float*)d_in[5];
    const float* lnb  = (const float*)d_in[6];
    float* y = (float*)d_out;

    cudaFuncSetAttribute(gemm_qkv,    cudaFuncAttributeMaxDynamicSharedMemorySize, QKV_DYN);
    cudaFuncSetAttribute(gemm_out_ln, cudaFuncAttributeMaxDynamicSharedMemorySize, OUT_SMEM);

    gemm_qkv<<<dim3(NTILES, 12, B), 256, QKV_DYN>>>(x, mem, Wqkv);
    k_stats_reduce<<<32, 256>>>();
    ctx_reduce<<<512, 256>>>();
    ctx_fold<<<dim3(4, NHEADS, B), 256>>>(Wout);
    gemm_out_ln<<<dim3(HW / 128, 1, B), 256, OUT_SMEM>>>(bout, lng, lnb, y);
}

// round 16
// speedup vs baseline: 1.2258x; 1.1058x over previous
#include <cuda_runtime.h>
#include <cuda_fp16.h>
#include <math.h>
#include <stdint.h>

#define B      16
#define C      256
#define HW     4096
#define MEM    64
#define NTOK   4160
#define H3     1536
#define HID    512
#define NHEADS 8
#define DH     64
#define NTILES 33      // n-tiles (also ctx partial chunks)

// -------- scratch (device globals, fully overwritten every launch) --------
__device__ float  g_ksump[NTILES * B * HID];       // per-n-tile partial sums of exp(k)
__device__ float  g_kinv[B * HID];                 // 1 / total sum
__device__ __half g_qexp_h[(size_t)B * HW * HID];  // softmaxed+scaled q, [b][t][hid] (t-major!)
__device__ float  g_ctxp[(size_t)NTILES * B * NHEADS * DH * DH];  // partial ctxT [nt][bh][e][d]
__device__ float  g_ctxT[B * NHEADS * DH * DH];    // ctxT [bh][e][d], inv applied
__device__ __half g_wc_h[(size_t)B * C * HID];     // folded weights [b][o][hid], fp16

// ---------------- mma helpers ----------------
__device__ __forceinline__ uint32_t f2tf32(float f) {
    uint32_t r;
    asm("cvt.rna.tf32.f32 %0, %1;" : "=r"(r) : "f"(f));
    return r;
}

__device__ __forceinline__ void mma_tf32(float* d, const uint32_t* a, const uint32_t* b) {
    asm volatile(
        "mma.sync.aligned.m16n8k8.row.col.f32.tf32.tf32.f32 "
        "{%0,%1,%2,%3}, {%4,%5,%6,%7}, {%8,%9}, {%0,%1,%2,%3};\n"
        : "+f"(d[0]), "+f"(d[1]), "+f"(d[2]), "+f"(d[3])
        : "r"(a[0]), "r"(a[1]), "r"(a[2]), "r"(a[3]), "r"(b[0]), "r"(b[1]));
}

__device__ __forceinline__ void mma_f16(float* d, const uint32_t* a, const uint32_t* b) {
    asm volatile(
        "mma.sync.aligned.m16n8k16.row.col.f32.f16.f16.f32 "
        "{%0,%1,%2,%3}, {%4,%5,%6,%7}, {%8,%9}, {%0,%1,%2,%3};\n"
        : "+f"(d[0]), "+f"(d[1]), "+f"(d[2]), "+f"(d[3])
        : "r"(a[0]), "r"(a[1]), "r"(a[2]), "r"(a[3]), "r"(b[0]), "r"(b[1]));
}

__device__ __forceinline__ void cp16(uint32_t dst, const void* src) {
    asm volatile("cp.async.cg.shared.global [%0], [%1], 16;\n" :: "r"(dst), "l"(src));
}
#define CP_COMMIT() asm volatile("cp.async.commit_group;\n")

// =====================================================================
// K1: fused qkv GEMM + attention front-end (tf32 MMA).
//  y<4 : q blocks   -> in-register softmax over d -> g_qexp_h (fp16,
//                      t-major via smem transpose)
//  y>=4: head blocks -> exp(k)+partial sums -> g_ksump; in-block 64x64x128
//                      context partial -> g_ctxp
// =====================================================================
#define QKV_DYN 67584

__global__ __launch_bounds__(256, 2) void gemm_qkv(
    const float* __restrict__ x, const float* __restrict__ mem,
    const float* __restrict__ W)
{
    extern __shared__ char dyn[];
    uint32_t (*As)[36]  = (uint32_t(*)[36])dyn;
    uint32_t (*Bs)[136] = (uint32_t(*)[136])(dyn + 18432);
    uint32_t (*Ks)[132] = (uint32_t(*)[132])dyn;             // alias (post-mainloop)
    uint32_t (*Vs)[132] = (uint32_t(*)[132])(dyn + 33792);
    __shared__ float psum[4][64];

    int b  = blockIdx.z;
    int y  = blockIdx.y;
    int nt = blockIdx.x;
    int n0 = nt * 128;
    bool is_q = (y < 4);
    int h = y - 4;
    int tid  = threadIdx.x;
    int lane = tid & 31, wid = tid >> 5;
    int warp_m = (wid & 1) * 64;
    int warp_n = (wid >> 1) * 32;
    int g = lane >> 2, tg = lane & 3;

    const float* src;
    int stride, col0, ncols;
    if (n0 < HW) { src = x + (size_t)b * C * HW; stride = HW;  col0 = n0; ncols = 128; }
    else {
        if (is_q) return;                // q not needed at memory tokens
        src = mem; stride = MEM; col0 = 0; ncols = MEM;
    }

    float acc[4][4][4];
    #pragma unroll
    for (int mf = 0; mf < 4; mf++)
        #pragma unroll
        for (int nf = 0; nf < 4; nf++)
            #pragma unroll
            for (int i = 0; i < 4; i++) acc[mf][nf][i] = 0.f;

    for (int k0 = 0; k0 < C; k0 += 32) {
        __syncthreads();
        #pragma unroll
        for (int r = 0; r < 4; r++) {
            int idx = tid + r * 256;
            int row = idx >> 3;
            int kc  = (idx & 7) * 4;
            int wrow;
            if (is_q) wrow = y * 128 + row;
            else      wrow = (row < 64) ? (HID + h * DH + row)
                                        : (2 * HID + h * DH + row - 64);
            float4 v = *(const float4*)(W + (size_t)wrow * C + k0 + kc);
            As[row][kc + 0] = f2tf32(v.x);
            As[row][kc + 1] = f2tf32(v.y);
            As[row][kc + 2] = f2tf32(v.z);
            As[row][kc + 3] = f2tf32(v.w);
        }
        #pragma unroll
        for (int r = 0; r < 4; r++) {
            int idx = tid + r * 256;
            int row = idx >> 5;
            int nc  = (idx & 31) * 4;
            float4 v;
            if (nc + 3 < ncols)
                v = *(const float4*)(src + (size_t)(k0 + row) * stride + col0 + nc);
            else
                v = make_float4(0.f, 0.f, 0.f, 0.f);
            Bs[row][nc + 0] = f2tf32(v.x);
            Bs[row][nc + 1] = f2tf32(v.y);
            Bs[row][nc + 2] = f2tf32(v.z);
            Bs[row][nc + 3] = f2tf32(v.w);
        }
        __syncthreads();
        #pragma unroll
        for (int ks = 0; ks < 4; ks++) {
            uint32_t a[4][4], bb[4][2];
            #pragma unroll
            for (int mf = 0; mf < 4; mf++) {
                int row = warp_m + mf * 16 + g;
                a[mf][0] = As[row    ][ks * 8 + tg];
                a[mf][1] = As[row + 8][ks * 8 + tg];
                a[mf][2] = As[row    ][ks * 8 + tg + 4];
                a[mf][3] = As[row + 8][ks * 8 + tg + 4];
            }
            #pragma unroll
            for (int nf = 0; nf < 4; nf++) {
                bb[nf][0] = Bs[ks * 8 + tg    ][warp_n + nf * 8 + g];
                bb[nf][1] = Bs[ks * 8 + tg + 4][warp_n + nf * 8 + g];
            }
            #pragma unroll
            for (int mf = 0; mf < 4; mf++)
                #pragma unroll
                for (int nf = 0; nf < 4; nf++)
                    mma_tf32(acc[mf][nf], a[mf], bb[nf]);
        }
    }
    __syncthreads();     // mainloop smem dead; safe to alias below

    if (is_q) {
        // ---- q: softmax over d (warp's 64 m-rows = one full head) ----
        #pragma unroll
        for (int nf = 0; nf < 4; nf++) {
            #pragma unroll
            for (int bc = 0; bc < 2; bc++) {
                float s = 0.f;
                #pragma unroll
                for (int mf = 0; mf < 4; mf++) {
                    float e0 = __expf(acc[mf][nf][bc]);
                    float e1 = __expf(acc[mf][nf][2 + bc]);
                    acc[mf][nf][bc]     = e0;
                    acc[mf][nf][2 + bc] = e1;
                    s += e0 + e1;
                }
                s += __shfl_xor_sync(0xffffffffu, s, 4);
                s += __shfl_xor_sync(0xffffffffu, s, 8);
                s += __shfl_xor_sync(0xffffffffu, s, 16);
                float sc = 0.125f / s;            // SCALE folded
                #pragma unroll
                for (int mf = 0; mf < 4; mf++) {
                    acc[mf][nf][bc]     *= sc;
                    acc[mf][nf][2 + bc] *= sc;
                }
            }
        }
        // stage [t][m] as half in smem, then coalesced t-major store
        __half (*sh)[144] = (__half(*)[144])dyn;
        #pragma unroll
        for (int mf = 0; mf < 4; mf++) {
            int ml = warp_m + mf * 16 + g;
            #pragma unroll
            for (int nf = 0; nf < 4; nf++) {
                int tl = warp_n + nf * 8 + tg * 2;
                sh[tl][ml]         = __float2half_rn(acc[mf][nf][0]);
                sh[tl + 1][ml]     = __float2half_rn(acc[mf][nf][1]);
                sh[tl][ml + 8]     = __float2half_rn(acc[mf][nf][2]);
                sh[tl + 1][ml + 8] = __float2half_rn(acc[mf][nf][3]);
            }
        }
        __syncthreads();
        __half* oph = g_qexp_h + ((size_t)b * HW + n0) * HID + y * 128;
        #pragma unroll
        for (int r = 0; r < 8; r++) {
            int c = tid + r * 256;           // 2048 16B chunks
            int tl = c >> 4, mc = (c & 15) * 8;
            *(float4*)(oph + (size_t)tl * HID + mc) = *(float4*)&sh[tl][mc];
        }
        return;
    }

    // ================= head block epilogue =================
    bool is_kw = ((wid & 1) == 0);       // warp holds k rows (0..63) else v rows
    if (is_kw) {
        #pragma unroll
        for (int mf = 0; mf < 4; mf++)
            #pragma unroll
            for (int nf = 0; nf < 4; nf++)
                #pragma unroll
                for (int i = 0; i < 4; i++)
                    acc[mf][nf][i] = __expf(acc[mf][nf][i]);

        #pragma unroll
        for (int mf = 0; mf < 4; mf++) {
            #pragma unroll
            for (int half = 0; half < 2; half++) {
                float s = 0.f;
                #pragma unroll
                for (int nf = 0; nf < 4; nf++) {
                    #pragma unroll
                    for (int bc = 0; bc < 2; bc++) {
                        int n = warp_n + nf * 8 + tg * 2 + bc;
                        float v = acc[mf][nf][half * 2 + bc];
                        s += (n0 + n < NTOK) ? v : 0.f;
                    }
                }
                s += __shfl_xor_sync(0xffffffffu, s, 1);
                s += __shfl_xor_sync(0xffffffffu, s, 2);
                if (tg == 0)
                    psum[wid >> 1][mf * 16 + g + half * 8] = s;
            }
        }
    }

    {
        uint32_t (*T)[132] = is_kw ? Ks : Vs;
        #pragma unroll
        for (int mf = 0; mf < 4; mf++) {
            int r = mf * 16 + g;
            #pragma unroll
            for (int nf = 0; nf < 4; nf++) {
                int ccol = warp_n + nf * 8 + tg * 2;
                T[r][ccol]         = f2tf32(acc[mf][nf][0]);
                T[r][ccol + 1]     = f2tf32(acc[mf][nf][1]);
                T[r + 8][ccol]     = f2tf32(acc[mf][nf][2]);
                T[r + 8][ccol + 1] = f2tf32(acc[mf][nf][3]);
            }
        }
    }
    __syncthreads();

    if (tid < 64) {
        float s = psum[0][tid] + psum[1][tid] + psum[2][tid] + psum[3][tid];
        g_ksump[(size_t)nt * (B * HID) + b * HID + h * DH + tid] = s;
    }

    // ---- in-block context partial: D[e][d] = sum_n Vs[e,n] * Ks[d,n] ----
    int we = (wid & 1) * 32;
    int wd = (wid >> 1) * 16;
    float acc2[2][2][4];
    #pragma unroll
    for (int mf = 0; mf < 2; mf++)
        #pragma unroll
        for (int nf = 0; nf < 2; nf++)
            #pragma unroll
            for (int i = 0; i < 4; i++) acc2[mf][nf][i] = 0.f;

    #pragma unroll
    for (int ks = 0; ks < 16; ks++) {
        uint32_t a[2][4], bb[2][2];
        #pragma unroll
        for (int mf = 0; mf < 2; mf++) {
            int row = we + mf * 16 + g;
            a[mf][0] = Vs[row    ][ks * 8 + tg];
            a[mf][1] = Vs[row + 8][ks * 8 + tg];
            a[mf][2] = Vs[row    ][ks * 8 + tg + 4];
            a[mf][3] = Vs[row + 8][ks * 8 + tg + 4];
        }
        #pragma unroll
        for (int nf = 0; nf < 2; nf++) {
            bb[nf][0] = Ks[wd + nf * 8 + g][ks * 8 + tg];
            bb[nf][1] = Ks[wd + nf * 8 + g][ks * 8 + tg + 4];
        }
        #pragma unroll
        for (int mf = 0; mf < 2; mf++)
            #pragma unroll
            for (int nf = 0; nf < 2; nf++)
                mma_tf32(acc2[mf][nf], a[mf], bb[nf]);
    }

    float* cp = g_ctxp + ((size_t)nt * (B * NHEADS) + b * NHEADS + h) * (DH * DH);
    #pragma unroll
    for (int mf = 0; mf < 2; mf++) {
        int e = we + mf * 16 + g;
        #pragma unroll
        for (int nf = 0; nf < 2; nf++) {
            int d = wd + nf * 8 + tg * 2;
            *(float2*)(cp + (size_t)e * DH + d)       = make_float2(acc2[mf][nf][0], acc2[mf][nf][1]);
            *(float2*)(cp + (size_t)(e + 8) * DH + d) = make_float2(acc2[mf][nf][2], acc2[mf][nf][3]);
        }
    }
}

// =====================================================================
// K2: reduce per-tile k sums -> g_kinv = 1/total   (8192 rows, 33 tiles)
// =====================================================================
__global__ __launch_bounds__(256) void k_stats_reduce()
{
    int row = blockIdx.x * 256 + threadIdx.x;     // 0..8191
    float s = 0.f;
    #pragma unroll
    for (int nt = 0; nt < NTILES; nt++)
        s += g_ksump[(size_t)nt * (B * HID) + row];
    g_kinv[row] = 1.f / s;
}

// =====================================================================
// K3: reduce 33 partial context chunks + apply 1/sum column scale
// =====================================================================
__global__ __launch_bounds__(256) void ctx_reduce()
{
    int idx = (blockIdx.x * 256 + threadIdx.x) * 4;    // 512 blocks covers 524288
    float4 s = *(const float4*)(g_ctxp + idx);
    #pragma unroll
    for (int ch = 1; ch < NTILES; ch++) {
        float4 v = *(const float4*)(g_ctxp + (size_t)ch * (B * NHEADS * DH * DH) + idx);
        s.x += v.x; s.y += v.y; s.z += v.z; s.w += v.w;
    }
    int bh = idx >> 12;          // 4096 elements per bh
    int d  = idx & 63;
    float4 inv = *(const float4*)(g_kinv + bh * 64 + d);
    s.x *= inv.x; s.y *= inv.y; s.z *= inv.z; s.w *= inv.w;
    *(float4*)(g_ctxT + idx) = s;
}

// =====================================================================
// K4: fold context into output weights (fp16 store):
//   Wc[b][o][h*64+d] = sum_e Wout[o][h*64+e] * ctxT[b,h][e][d]
// =====================================================================
__global__ __launch_bounds__(256) void ctx_fold(const float* __restrict__ Wout)
{
    __shared__ float ctx_s[64][68];      // [e][d]
    __shared__ float w_s[64][68];        // [o_local][e]

    int o0 = blockIdx.x * 64;
    int h  = blockIdx.y;
    int b  = blockIdx.z;
    int bh = b * NHEADS + h;
    int tid = threadIdx.x;

    const float* cp = g_ctxT + (size_t)bh * DH * DH;
    #pragma unroll
    for (int r = 0; r < 4; r++) {
        int f = tid + r * 256;
        int row = f >> 4, c4 = (f & 15) * 4;
        *(float4*)&ctx_s[row][c4] = *(const float4*)(cp + (size_t)row * DH + c4);
        *(float4*)&w_s[row][c4]   = *(const float4*)(Wout + (size_t)(o0 + row) * HID + h * DH + c4);
    }
    __syncthreads();

    int og = tid >> 6;
    int d  = tid & 63;
    float acc[16];
    #pragma unroll
    for (int i = 0; i < 16; i++) acc[i] = 0.f;
    #pragma unroll 4
    for (int e = 0; e < 64; e++) {
        float c = ctx_s[e][d];
        #pragma unroll
        for (int i = 0; i < 16; i++)
            acc[i] = fmaf(w_s[og * 16 + i][e], c, acc[i]);
    }
    __half* wcp = g_wc_h + ((size_t)b * C) * HID;
    #pragma unroll
    for (int i = 0; i < 16; i++)
        wcp[(size_t)(o0 + og * 16 + i) * HID + h * DH + d] = __float2half_rn(acc[i]);
}

// =====================================================================
// K5: y = LN( Wc_b @ qexp + bias )   fp16 m16n8k16, M=256 N=128 K=512,
// cp.async 2-stage pipeline. A: g_wc_h [o][k] row-major; B: g_qexp_h
// [t][k] (k-contiguous = .col operand layout).
// =====================================================================
#define OUT_A_BYTES (256 * 40 * 2)                  // 20480
#define OUT_STAGE   (OUT_A_BYTES + 128 * 40 * 2)    // 20480 + 10240 = 30720
#define OUT_SMEM    (2 * OUT_STAGE + 8192)          // 69632

__global__ __launch_bounds__(256) void gemm_out_ln(
    const float* __restrict__ bias, const float* __restrict__ lng,
    const float* __restrict__ lnb, float* __restrict__ y)
{
    extern __shared__ char dyn[];
    float* swsum = (float*)(dyn + 2 * OUT_STAGE);            // 4x128
    float* swsq  = (float*)(dyn + 2 * OUT_STAGE + 2048);     // 4x128
    float* sbias = (float*)(dyn + 2 * OUT_STAGE + 4096);     // 256
    float* slg   = (float*)(dyn + 2 * OUT_STAGE + 5120);     // 256
    float* slb   = (float*)(dyn + 2 * OUT_STAGE + 6144);     // 256
    float* smean = (float*)(dyn + 2 * OUT_STAGE + 7168);     // 128
    float* srstd = (float*)(dyn + 2 * OUT_STAGE + 7680);     // 128

    int t0 = blockIdx.x * 128;
    int b  = blockIdx.z;
    int tid  = threadIdx.x;
    int lane = tid & 31, wid = tid >> 5;
    int g = lane >> 2, tg = lane & 3;
    int wm = wid & 3;
    int wn = wid >> 2;

    sbias[tid] = bias[tid];
    slg[tid]   = lng[tid];
    slb[tid]   = lnb[tid];

    const __half* Ap = g_wc_h + (size_t)b * C * HID;
    const __half* Bp = g_qexp_h + (size_t)b * HW * HID;
    uint32_t sbase = (uint32_t)__cvta_generic_to_shared(dyn);

    auto PREFETCH = [&](int t) {        // k-tile t (32 halves) -> buffer t&1
        int k0 = t * 32;
        uint32_t abase = sbase + (t & 1) * OUT_STAGE;
        uint32_t bbase = abase + OUT_A_BYTES;
        #pragma unroll
        for (int r = 0; r < 4; r++) {
            int idx = tid + r * 256;     // 1024 chunks of 8 halves for A
            int row = idx >> 2, kc = (idx & 3) * 8;
            cp16(abase + (row * 40 + kc) * 2, Ap + (size_t)row * HID + k0 + kc);
        }
        #pragma unroll
        for (int r = 0; r < 2; r++) {
            int idx = tid + r * 256;     // 512 chunks for B
            int row = idx >> 2, kc = (idx & 3) * 8;
            cp16(bbase + (row * 40 + kc) * 2, Bp + (size_t)(t0 + row) * HID + k0 + kc);
        }
        CP_COMMIT();
    };

    float acc[4][8][4];
    #pragma unroll
    for (int mf = 0; mf < 4; mf++)
        #pragma unroll
        for (int nf = 0; nf < 8; nf++)
            #pragma unroll
            for (int i = 0; i < 4; i++) acc[mf][nf][i] = 0.f;

    PREFETCH(0);

    #pragma unroll 2
    for (int t = 0; t < 16; t++) {                  // 16 k-tiles of 32
        if (t + 1 < 16) {
            PREFETCH(t + 1);
            asm volatile("cp.async.wait_group 1;\n" ::: "memory");
        } else {
            asm volatile("cp.async.wait_group 0;\n" ::: "memory");
        }
        __syncthreads();

        uint32_t (*A32)[20] = (uint32_t(*)[20])(dyn + (t & 1) * OUT_STAGE);
        uint32_t (*B32)[20] = (uint32_t(*)[20])(dyn + (t & 1) * OUT_STAGE + OUT_A_BYTES);
        #pragma unroll
        for (int ks = 0; ks < 2; ks++) {            // k=16 per mma
            uint32_t a[4][4], bb[8][2];
            #pragma unroll
            for (int mf = 0; mf < 4; mf++) {
                int row = wm * 64 + mf * 16 + g;
                a[mf][0] = A32[row    ][ks * 8 + tg];
                a[mf][1] = A32[row + 8][ks * 8 + tg];
                a[mf][2] = A32[row    ][ks * 8 + tg + 4];
                a[mf][3] = A32[row + 8][ks * 8 + tg + 4];
            }
            #pragma unroll
            for (int nf = 0; nf < 8; nf++) {
                int col = wn * 64 + nf * 8 + g;
                bb[nf][0] = B32[col][ks * 8 + tg];
                bb[nf][1] = B32[col][ks * 8 + tg + 4];
            }
            #pragma unroll
            for (int mf = 0; mf < 4; mf++)
                #pragma unroll
                for (int nf = 0; nf < 8; nf++)
                    mma_f16(acc[mf][nf], a[mf], bb[nf]);
        }
        __syncthreads();
    }

    // ---- LayerNorm over o=256 per token ----
    float psum[16], psq[16];
    #pragma unroll
    for (int j = 0; j < 16; j++) { psum[j] = 0.f; psq[j] = 0.f; }
    #pragma unroll
    for (int mf = 0; mf < 4; mf++) {
        int o0r = wm * 64 + mf * 16 + g;
        float b0 = sbias[o0r], b1 = sbias[o0r + 8];
        #pragma unroll
        for (int nf = 0; nf < 8; nf++) {
            #pragma unroll
            for (int bc = 0; bc < 2; bc++) {
                float v0 = acc[mf][nf][bc]     + b0;
                float v1 = acc[mf][nf][2 + bc] + b1;
                psum[nf * 2 + bc] += v0 + v1;
                psq[nf * 2 + bc]  += v0 * v0 + v1 * v1;
            }
        }
    }
    #pragma unroll
    for (int o = 4; o <= 16; o <<= 1) {
        #pragma unroll
        for (int j = 0; j < 16; j++) {
            psum[j] += __shfl_xor_sync(0xffffffffu, psum[j], o);
            psq[j]  += __shfl_xor_sync(0xffffffffu, psq[j], o);
        }
    }
    __syncthreads();
    if (g == 0) {
        #pragma unroll
        for (int nf = 0; nf < 8; nf++)
            #pragma unroll
            for (int bc = 0; bc < 2; bc++) {
                int tl = wn * 64 + nf * 8 + tg * 2 + bc;
                swsum[wm * 128 + tl] = psum[nf * 2 + bc];
                swsq[wm * 128 + tl]  = psq[nf * 2 + bc];
            }
    }
    __syncthreads();
    if (tid < 128) {
        float s  = swsum[tid] + swsum[128 + tid] + swsum[256 + tid] + swsum[384 + tid];
        float sq = swsq[tid]  + swsq[128 + tid]  + swsq[256 + tid]  + swsq[384 + tid];
        float mean = s * (1.f / 256.f);
        float var  = sq * (1.f / 256.f) - mean * mean;
        smean[tid] = mean;
        srstd[tid] = rsqrtf(var + 1e-5f);
    }
    __syncthreads();

    float* outp = y + (size_t)b * C * HW;
    #pragma unroll
    for (int mf = 0; mf < 4; mf++) {
        int o0r = wm * 64 + mf * 16 + g;
        float b0 = sbias[o0r],   g0 = slg[o0r],   be0 = slb[o0r];
        float b1 = sbias[o0r+8], g1 = slg[o0r+8], be1 = slb[o0r+8];
        #pragma unroll
        for (int nf = 0; nf < 8; nf++) {
            int tl = wn * 64 + nf * 8 + tg * 2;
            float m0 = smean[tl], m1 = smean[tl + 1];
            float r0 = srstd[tl], r1 = srstd[tl + 1];
            float2 v0, v1;
            v0.x = (acc[mf][nf][0] + b0 - m0) * r0 * g0 + be0;
            v0.y = (acc[mf][nf][1] + b0 - m1) * r1 * g0 + be0;
            v1.x = (acc[mf][nf][2] + b1 - m0) * r0 * g1 + be1;
            v1.y = (acc[mf][nf][3] + b1 - m1) * r1 * g1 + be1;
            *(float2*)(outp + (size_t)o0r * HW + t0 + tl)       = v0;
            *(float2*)(outp + (size_t)(o0r + 8) * HW + t0 + tl) = v1;
        }
    }
}

// =====================================================================
extern "C" void kernel_launch(void* const* d_in, const int* in_sizes, int n_in,
                              void* d_out, int out_size)
{
    const float* x    = (const float*)d_in[0];
    const float* mem  = (const float*)d_in[1];
    const float* Wqkv = (const float*)d_in[2];
    const float* Wout = (const float*)d_in[3];
    const float* bout = (const float*)d_in[4];
    const float* lng  = (const float*)d_in[5];
    const float* lnb  = (const float*)d_in[6];
    float* y = (float*)d_out;

    cudaFuncSetAttribute(gemm_qkv,    cudaFuncAttributeMaxDynamicSharedMemorySize, QKV_DYN);
    cudaFuncSetAttribute(gemm_out_ln, cudaFuncAttributeMaxDynamicSharedMemorySize, OUT_SMEM);

    gemm_qkv<<<dim3(NTILES, 12, B), 256, QKV_DYN>>>(x, mem, Wqkv);
    k_stats_reduce<<<32, 256>>>();
    ctx_reduce<<<512, 256>>>();
    ctx_fold<<<dim3(4, NHEADS, B), 256>>>(Wout);
    gemm_out_ln<<<dim3(HW / 128, 1, B), 256, OUT_SMEM>>>(bout, lng, lnb, y);
}

// round 17
// speedup vs baseline: 1.5379x; 1.2545x over previous
#include <cuda_runtime.h>
#include <cuda_fp16.h>
#include <math.h>
#include <stdint.h>

#define B      16
#define C      256
#define HW     4096
#define MEM    64
#define NTOK   4160
#define H3     1536
#define HID    512
#define NHEADS 8
#define DH     64
#define NTILES 33      // n-tiles (also ctx partial chunks)

// -------- scratch (device globals, fully overwritten every launch) --------
__device__ float  g_ksump[NTILES * B * HID];       // per-n-tile partial sums of exp(k)
__device__ float  g_kinv[B * HID];                 // 1 / total sum
__device__ __half g_qexp_h[(size_t)B * HW * HID];  // softmaxed+scaled q, [b][t][hid] (t-major)
__device__ float  g_ctxp[(size_t)NTILES * B * NHEADS * DH * DH];  // partial ctxT [nt][bh][e][d]
__device__ float  g_ctxT[B * NHEADS * DH * DH];    // ctxT [bh][e][d], inv applied
__device__ __half g_wc_h[(size_t)B * C * HID];     // folded weights [b][o][hid], fp16

// ---------------- mma helpers ----------------
__device__ __forceinline__ uint32_t f2tf32(float f) {
    uint32_t r;
    asm("cvt.rna.tf32.f32 %0, %1;" : "=r"(r) : "f"(f));
    return r;
}

__device__ __forceinline__ void mma_tf32(float* d, const uint32_t* a, const uint32_t* b) {
    asm volatile(
        "mma.sync.aligned.m16n8k8.row.col.f32.tf32.tf32.f32 "
        "{%0,%1,%2,%3}, {%4,%5,%6,%7}, {%8,%9}, {%0,%1,%2,%3};\n"
        : "+f"(d[0]), "+f"(d[1]), "+f"(d[2]), "+f"(d[3])
        : "r"(a[0]), "r"(a[1]), "r"(a[2]), "r"(a[3]), "r"(b[0]), "r"(b[1]));
}

__device__ __forceinline__ void mma_f16(float* d, const uint32_t* a, const uint32_t* b) {
    asm volatile(
        "mma.sync.aligned.m16n8k16.row.col.f32.f16.f16.f32 "
        "{%0,%1,%2,%3}, {%4,%5,%6,%7}, {%8,%9}, {%0,%1,%2,%3};\n"
        : "+f"(d[0]), "+f"(d[1]), "+f"(d[2]), "+f"(d[3])
        : "r"(a[0]), "r"(a[1]), "r"(a[2]), "r"(a[3]), "r"(b[0]), "r"(b[1]));
}

__device__ __forceinline__ void ldsm4(uint32_t* r, uint32_t addr) {
    asm volatile("ldmatrix.sync.aligned.m8n8.x4.shared.b16 {%0,%1,%2,%3}, [%4];\n"
        : "=r"(r[0]), "=r"(r[1]), "=r"(r[2]), "=r"(r[3]) : "r"(addr));
}
__device__ __forceinline__ void ldsm4t(uint32_t* r, uint32_t addr) {
    asm volatile("ldmatrix.sync.aligned.m8n8.x4.trans.shared.b16 {%0,%1,%2,%3}, [%4];\n"
        : "=r"(r[0]), "=r"(r[1]), "=r"(r[2]), "=r"(r[3]) : "r"(addr));
}

__device__ __forceinline__ void cp16(uint32_t dst, const void* src) {
    asm volatile("cp.async.cg.shared.global [%0], [%1], 16;\n" :: "r"(dst), "l"(src));
}
#define CP_COMMIT() asm volatile("cp.async.commit_group;\n")

// =====================================================================
// K1: fused qkv GEMM + attention front-end — fp16 m16n8k16 mainloop
// with ldmatrix operand fetch.
//  A: As_h[m=128][k pad 40] fp16 row-major (non-trans ldmatrix)
//  B: Bs_h[k=32][n=128+pad8] fp16 (trans ldmatrix)
//  y<4 : q blocks   -> in-register softmax over d -> g_qexp_h (t-major)
//  y>=4: head blocks -> exp(k)+partial sums; in-block ctx partial (tf32)
// =====================================================================
#define QKV_DYN 67584
#define BS_OFF  10240            // Bs_h offset in dyn smem

__global__ __launch_bounds__(256, 2) void gemm_qkv(
    const float* __restrict__ x, const float* __restrict__ mem,
    const float* __restrict__ W)
{
    extern __shared__ char dyn[];
    __half (*As_h)[40]  = (__half(*)[40])dyn;                // 128*40*2 = 10240 B
    __half (*Bs_h)[136] = (__half(*)[136])(dyn + BS_OFF);    // 32*136*2 = 8704 B
    uint32_t (*Ks)[132] = (uint32_t(*)[132])dyn;             // alias (post-mainloop)
    uint32_t (*Vs)[132] = (uint32_t(*)[132])(dyn + 33792);
    __shared__ float psum[4][64];

    int b  = blockIdx.z;
    int y  = blockIdx.y;
    int nt = blockIdx.x;
    int n0 = nt * 128;
    bool is_q = (y < 4);
    int h = y - 4;
    int tid  = threadIdx.x;
    int lane = tid & 31, wid = tid >> 5;
    int warp_m = (wid & 1) * 64;
    int warp_n = (wid >> 1) * 32;
    int g = lane >> 2, tg = lane & 3;

    const float* src;
    int stride, col0, ncols;
    if (n0 < HW) { src = x + (size_t)b * C * HW; stride = HW;  col0 = n0; ncols = 128; }
    else {
        if (is_q) return;                // q not needed at memory tokens
        src = mem; stride = MEM; col0 = 0; ncols = MEM;
    }

    uint32_t sm = (uint32_t)__cvta_generic_to_shared(dyn);
    int t4 = lane >> 3, rrow = lane & 7;
    uint32_t a_addr = sm + (uint32_t)(((warp_m + (t4 & 1) * 8 + rrow) * 40 + (t4 >> 1) * 8) * 2);
    uint32_t b_addr = sm + BS_OFF +
        (uint32_t)((((t4 & 1) * 8 + rrow) * 136 + warp_n + (t4 >> 1) * 8) * 2);

    float acc[4][4][4];
    #pragma unroll
    for (int mf = 0; mf < 4; mf++)
        #pragma unroll
        for (int nf = 0; nf < 4; nf++)
            #pragma unroll
            for (int i = 0; i < 4; i++) acc[mf][nf][i] = 0.f;

    for (int k0 = 0; k0 < C; k0 += 32) {
        __syncthreads();
        #pragma unroll
        for (int r = 0; r < 4; r++) {
            int idx = tid + r * 256;
            int row = idx >> 3;
            int kc  = (idx & 7) * 4;
            int wrow;
            if (is_q) wrow = y * 128 + row;
            else      wrow = (row < 64) ? (HID + h * DH + row)
                                        : (2 * HID + h * DH + row - 64);
            float4 v = *(const float4*)(W + (size_t)wrow * C + k0 + kc);
            __half2* p = (__half2*)&As_h[row][kc];
            p[0] = __floats2half2_rn(v.x, v.y);
            p[1] = __floats2half2_rn(v.z, v.w);
        }
        #pragma unroll
        for (int r = 0; r < 4; r++) {
            int idx = tid + r * 256;
            int row = idx >> 5;
            int nc  = (idx & 31) * 4;
            float4 v;
            if (nc + 3 < ncols)
                v = *(const float4*)(src + (size_t)(k0 + row) * stride + col0 + nc);
            else
                v = make_float4(0.f, 0.f, 0.f, 0.f);
            __half2* p = (__half2*)&Bs_h[row][nc];
            p[0] = __floats2half2_rn(v.x, v.y);
            p[1] = __floats2half2_rn(v.z, v.w);
        }
        __syncthreads();
        #pragma unroll
        for (int ks = 0; ks < 2; ks++) {            // k=16 per mma
            uint32_t a[4][4], bb[4][2];
            #pragma unroll
            for (int mf = 0; mf < 4; mf++)
                ldsm4(a[mf], a_addr + mf * 1280 + ks * 32);
            ldsm4t(&bb[0][0], b_addr + ks * 4352);          // nf0,nf1 (n+0..15)
            ldsm4t(&bb[2][0], b_addr + ks * 4352 + 32);     // nf2,nf3 (n+16..31)
            #pragma unroll
            for (int mf = 0; mf < 4; mf++)
                #pragma unroll
                for (int nf = 0; nf < 4; nf++)
                    mma_f16(acc[mf][nf], a[mf], bb[nf]);
        }
    }
    __syncthreads();     // mainloop smem dead; safe to alias below

    if (is_q) {
        // ---- q: softmax over d (warp's 64 m-rows = one full head) ----
        #pragma unroll
        for (int nf = 0; nf < 4; nf++) {
            #pragma unroll
            for (int bc = 0; bc < 2; bc++) {
                float s = 0.f;
                #pragma unroll
                for (int mf = 0; mf < 4; mf++) {
                    float e0 = __expf(acc[mf][nf][bc]);
                    float e1 = __expf(acc[mf][nf][2 + bc]);
                    acc[mf][nf][bc]     = e0;
                    acc[mf][nf][2 + bc] = e1;
                    s += e0 + e1;
                }
                s += __shfl_xor_sync(0xffffffffu, s, 4);
                s += __shfl_xor_sync(0xffffffffu, s, 8);
                s += __shfl_xor_sync(0xffffffffu, s, 16);
                float sc = 0.125f / s;            // SCALE folded
                #pragma unroll
                for (int mf = 0; mf < 4; mf++) {
                    acc[mf][nf][bc]     *= sc;
                    acc[mf][nf][2 + bc] *= sc;
                }
            }
        }
        // stage [t][m] as half in smem, then coalesced t-major store
        __half (*sh)[144] = (__half(*)[144])dyn;
        #pragma unroll
        for (int mf = 0; mf < 4; mf++) {
            int ml = warp_m + mf * 16 + g;
            #pragma unroll
            for (int nf = 0; nf < 4; nf++) {
                int tl = warp_n + nf * 8 + tg * 2;
                sh[tl][ml]         = __float2half_rn(acc[mf][nf][0]);
                sh[tl + 1][ml]     = __float2half_rn(acc[mf][nf][1]);
                sh[tl][ml + 8]     = __float2half_rn(acc[mf][nf][2]);
                sh[tl + 1][ml + 8] = __float2half_rn(acc[mf][nf][3]);
            }
        }
        __syncthreads();
        __half* oph = g_qexp_h + ((size_t)b * HW + n0) * HID + y * 128;
        #pragma unroll
        for (int r = 0; r < 8; r++) {
            int c = tid + r * 256;           // 2048 16B chunks
            int tl = c >> 4, mc = (c & 15) * 8;
            *(float4*)(oph + (size_t)tl * HID + mc) = *(float4*)&sh[tl][mc];
        }
        return;
    }

    // ================= head block epilogue =================
    bool is_kw = ((wid & 1) == 0);       // warp holds k rows (0..63) else v rows
    if (is_kw) {
        #pragma unroll
        for (int mf = 0; mf < 4; mf++)
            #pragma unroll
            for (int nf = 0; nf < 4; nf++)
                #pragma unroll
                for (int i = 0; i < 4; i++)
                    acc[mf][nf][i] = __expf(acc[mf][nf][i]);

        #pragma unroll
        for (int mf = 0; mf < 4; mf++) {
            #pragma unroll
            for (int half = 0; half < 2; half++) {
                float s = 0.f;
                #pragma unroll
                for (int nf = 0; nf < 4; nf++) {
                    #pragma unroll
                    for (int bc = 0; bc < 2; bc++) {
                        int n = warp_n + nf * 8 + tg * 2 + bc;
                        float v = acc[mf][nf][half * 2 + bc];
                        s += (n0 + n < NTOK) ? v : 0.f;
                    }
                }
                s += __shfl_xor_sync(0xffffffffu, s, 1);
                s += __shfl_xor_sync(0xffffffffu, s, 2);
                if (tg == 0)
                    psum[wid >> 1][mf * 16 + g + half * 8] = s;
            }
        }
    }

    {
        uint32_t (*T)[132] = is_kw ? Ks : Vs;
        #pragma unroll
        for (int mf = 0; mf < 4; mf++) {
            int r = mf * 16 + g;
            #pragma unroll
            for (int nf = 0; nf < 4; nf++) {
                int ccol = warp_n + nf * 8 + tg * 2;
                T[r][ccol]         = f2tf32(acc[mf][nf][0]);
                T[r][ccol + 1]     = f2tf32(acc[mf][nf][1]);
                T[r + 8][ccol]     = f2tf32(acc[mf][nf][2]);
                T[r + 8][ccol + 1] = f2tf32(acc[mf][nf][3]);
            }
        }
    }
    __syncthreads();

    if (tid < 64) {
        float s = psum[0][tid] + psum[1][tid] + psum[2][tid] + psum[3][tid];
        g_ksump[(size_t)nt * (B * HID) + b * HID + h * DH + tid] = s;
    }

    // ---- in-block context partial: D[e][d] = sum_n Vs[e,n] * Ks[d,n] ----
    int we = (wid & 1) * 32;
    int wd = (wid >> 1) * 16;
    float acc2[2][2][4];
    #pragma unroll
    for (int mf = 0; mf < 2; mf++)
        #pragma unroll
        for (int nf = 0; nf < 2; nf++)
            #pragma unroll
            for (int i = 0; i < 4; i++) acc2[mf][nf][i] = 0.f;

    #pragma unroll
    for (int ks = 0; ks < 16; ks++) {
        uint32_t a[2][4], bb[2][2];
        #pragma unroll
        for (int mf = 0; mf < 2; mf++) {
            int row = we + mf * 16 + g;
            a[mf][0] = Vs[row    ][ks * 8 + tg];
            a[mf][1] = Vs[row + 8][ks * 8 + tg];
            a[mf][2] = Vs[row    ][ks * 8 + tg + 4];
            a[mf][3] = Vs[row + 8][ks * 8 + tg + 4];
        }
        #pragma unroll
        for (int nf = 0; nf < 2; nf++) {
            bb[nf][0] = Ks[wd + nf * 8 + g][ks * 8 + tg];
            bb[nf][1] = Ks[wd + nf * 8 + g][ks * 8 + tg + 4];
        }
        #pragma unroll
        for (int mf = 0; mf < 2; mf++)
            #pragma unroll
            for (int nf = 0; nf < 2; nf++)
                mma_tf32(acc2[mf][nf], a[mf], bb[nf]);
    }

    float* cp = g_ctxp + ((size_t)nt * (B * NHEADS) + b * NHEADS + h) * (DH * DH);
    #pragma unroll
    for (int mf = 0; mf < 2; mf++) {
        int e = we + mf * 16 + g;
        #pragma unroll
        for (int nf = 0; nf < 2; nf++) {
            int d = wd + nf * 8 + tg * 2;
            *(float2*)(cp + (size_t)e * DH + d)       = make_float2(acc2[mf][nf][0], acc2[mf][nf][1]);
            *(float2*)(cp + (size_t)(e + 8) * DH + d) = make_float2(acc2[mf][nf][2], acc2[mf][nf][3]);
        }
    }
}

// =====================================================================
// K2: reduce per-tile k sums -> g_kinv = 1/total   (8192 rows, 33 tiles)
// =====================================================================
__global__ __launch_bounds__(256) void k_stats_reduce()
{
    int row = blockIdx.x * 256 + threadIdx.x;     // 0..8191
    float s = 0.f;
    #pragma unroll
    for (int nt = 0; nt < NTILES; nt++)
        s += g_ksump[(size_t)nt * (B * HID) + row];
    g_kinv[row] = 1.f / s;
}

// =====================================================================
// K3: reduce 33 partial context chunks + apply 1/sum column scale
// =====================================================================
__global__ __launch_bounds__(256) void ctx_reduce()
{
    int idx = (blockIdx.x * 256 + threadIdx.x) * 4;    // 512 blocks covers 524288
    float4 s = *(const float4*)(g_ctxp + idx);
    #pragma unroll
    for (int ch = 1; ch < NTILES; ch++) {
        float4 v = *(const float4*)(g_ctxp + (size_t)ch * (B * NHEADS * DH * DH) + idx);
        s.x += v.x; s.y += v.y; s.z += v.z; s.w += v.w;
    }
    int bh = idx >> 12;          // 4096 elements per bh
    int d  = idx & 63;
    float4 inv = *(const float4*)(g_kinv + bh * 64 + d);
    s.x *= inv.x; s.y *= inv.y; s.z *= inv.z; s.w *= inv.w;
    *(float4*)(g_ctxT + idx) = s;
}

// =====================================================================
// K4: fold context into output weights (fp16 store):
//   Wc[b][o][h*64+d] = sum_e Wout[o][h*64+e] * ctxT[b,h][e][d]
// =====================================================================
__global__ __launch_bounds__(256) void ctx_fold(const float* __restrict__ Wout)
{
    __shared__ float ctx_s[64][68];      // [e][d]
    __shared__ float w_s[64][68];        // [o_local][e]

    int o0 = blockIdx.x * 64;
    int h  = blockIdx.y;
    int b  = blockIdx.z;
    int bh = b * NHEADS + h;
    int tid = threadIdx.x;

    const float* cp = g_ctxT + (size_t)bh * DH * DH;
    #pragma unroll
    for (int r = 0; r < 4; r++) {
        int f = tid + r * 256;
        int row = f >> 4, c4 = (f & 15) * 4;
        *(float4*)&ctx_s[row][c4] = *(const float4*)(cp + (size_t)row * DH + c4);
        *(float4*)&w_s[row][c4]   = *(const float4*)(Wout + (size_t)(o0 + row) * HID + h * DH + c4);
    }
    __syncthreads();

    int og = tid >> 6;
    int d  = tid & 63;
    float acc[16];
    #pragma unroll
    for (int i = 0; i < 16; i++) acc[i] = 0.f;
    #pragma unroll 4
    for (int e = 0; e < 64; e++) {
        float c = ctx_s[e][d];
        #pragma unroll
        for (int i = 0; i < 16; i++)
            acc[i] = fmaf(w_s[og * 16 + i][e], c, acc[i]);
    }
    __half* wcp = g_wc_h + ((size_t)b * C) * HID;
    #pragma unroll
    for (int i = 0; i < 16; i++)
        wcp[(size_t)(o0 + og * 16 + i) * HID + h * DH + d] = __float2half_rn(acc[i]);
}

// =====================================================================
// K5: y = LN( Wc_b @ qexp + bias )   fp16 m16n8k16, M=256 N=128 K=512,
// cp.async 2-stage pipeline.
// =====================================================================
#define OUT_A_BYTES (256 * 40 * 2)                  // 20480
#define OUT_STAGE   (OUT_A_BYTES + 128 * 40 * 2)    // 20480 + 10240 = 30720
#define OUT_SMEM    (2 * OUT_STAGE + 8192)          // 69632

__global__ __launch_bounds__(256) void gemm_out_ln(
    const float* __restrict__ bias, const float* __restrict__ lng,
    const float* __restrict__ lnb, float* __restrict__ y)
{
    extern __shared__ char dyn[];
    float* swsum = (float*)(dyn + 2 * OUT_STAGE);            // 4x128
    float* swsq  = (float*)(dyn + 2 * OUT_STAGE + 2048);     // 4x128
    float* sbias = (float*)(dyn + 2 * OUT_STAGE + 4096);     // 256
    float* slg   = (float*)(dyn + 2 * OUT_STAGE + 5120);     // 256
    float* slb   = (float*)(dyn + 2 * OUT_STAGE + 6144);     // 256
    float* smean = (float*)(dyn + 2 * OUT_STAGE + 7168);     // 128
    float* srstd = (float*)(dyn + 2 * OUT_STAGE + 7680);     // 128

    int t0 = blockIdx.x * 128;
    int b  = blockIdx.z;
    int tid  = threadIdx.x;
    int lane = tid & 31, wid = tid >> 5;
    int g = lane >> 2, tg = lane & 3;
    int wm = wid & 3;
    int wn = wid >> 2;

    sbias[tid] = bias[tid];
    slg[tid]   = lng[tid];
    slb[tid]   = lnb[tid];

    const __half* Ap = g_wc_h + (size_t)b * C * HID;
    const __half* Bp = g_qexp_h + (size_t)b * HW * HID;
    uint32_t sbase = (uint32_t)__cvta_generic_to_shared(dyn);

    auto PREFETCH = [&](int t) {        // k-tile t (32 halves) -> buffer t&1
        int k0 = t * 32;
        uint32_t abase = sbase + (t & 1) * OUT_STAGE;
        uint32_t bbase = abase + OUT_A_BYTES;
        #pragma unroll
        for (int r = 0; r < 4; r++) {
            int idx = tid + r * 256;     // 1024 chunks of 8 halves for A
            int row = idx >> 2, kc = (idx & 3) * 8;
            cp16(abase + (row * 40 + kc) * 2, Ap + (size_t)row * HID + k0 + kc);
        }
        #pragma unroll
        for (int r = 0; r < 2; r++) {
            int idx = tid + r * 256;     // 512 chunks for B
            int row = idx >> 2, kc = (idx & 3) * 8;
            cp16(bbase + (row * 40 + kc) * 2, Bp + (size_t)(t0 + row) * HID + k0 + kc);
        }
        CP_COMMIT();
    };

    float acc[4][8][4];
    #pragma unroll
    for (int mf = 0; mf < 4; mf++)
        #pragma unroll
        for (int nf = 0; nf < 8; nf++)
            #pragma unroll
            for (int i = 0; i < 4; i++) acc[mf][nf][i] = 0.f;

    PREFETCH(0);

    #pragma unroll 2
    for (int t = 0; t < 16; t++) {                  // 16 k-tiles of 32
        if (t + 1 < 16) {
            PREFETCH(t + 1);
            asm volatile("cp.async.wait_group 1;\n" ::: "memory");
        } else {
            asm volatile("cp.async.wait_group 0;\n" ::: "memory");
        }
        __syncthreads();

        uint32_t (*A32)[20] = (uint32_t(*)[20])(dyn + (t & 1) * OUT_STAGE);
        uint32_t (*B32)[20] = (uint32_t(*)[20])(dyn + (t & 1) * OUT_STAGE + OUT_A_BYTES);
        #pragma unroll
        for (int ks = 0; ks < 2; ks++) {            // k=16 per mma
            uint32_t a[4][4], bb[8][2];
            #pragma unroll
            for (int mf = 0; mf < 4; mf++) {
                int row = wm * 64 + mf * 16 + g;
                a[mf][0] = A32[row    ][ks * 8 + tg];
                a[mf][1] = A32[row + 8][ks * 8 + tg];
                a[mf][2] = A32[row    ][ks * 8 + tg + 4];
                a[mf][3] = A32[row + 8][ks * 8 + tg + 4];
            }
            #pragma unroll
            for (int nf = 0; nf < 8; nf++) {
                int col = wn * 64 + nf * 8 + g;
                bb[nf][0] = B32[col][ks * 8 + tg];
                bb[nf][1] = B32[col][ks * 8 + tg + 4];
            }
            #pragma unroll
            for (int mf = 0; mf < 4; mf++)
                #pragma unroll
                for (int nf = 0; nf < 8; nf++)
                    mma_f16(acc[mf][nf], a[mf], bb[nf]);
        }
        __syncthreads();
    }

    // ---- LayerNorm over o=256 per token ----
    float psum[16], psq[16];
    #pragma unroll
    for (int j = 0; j < 16; j++) { psum[j] = 0.f; psq[j] = 0.f; }
    #pragma unroll
    for (int mf = 0; mf < 4; mf++) {
        int o0r = wm * 64 + mf * 16 + g;
        float b0 = sbias[o0r], b1 = sbias[o0r + 8];
        #pragma unroll
        for (int nf = 0; nf < 8; nf++) {
            #pragma unroll
            for (int bc = 0; bc < 2; bc++) {
                float v0 = acc[mf][nf][bc]     + b0;
                float v1 = acc[mf][nf][2 + bc] + b1;
                psum[nf * 2 + bc] += v0 + v1;
                psq[nf * 2 + bc]  += v0 * v0 + v1 * v1;
            }
        }
    }
    #pragma unroll
    for (int o = 4; o <= 16; o <<= 1) {
        #pragma unroll
        for (int j = 0; j < 16; j++) {
            psum[j] += __shfl_xor_sync(0xffffffffu, psum[j], o);
            psq[j]  += __shfl_xor_sync(0xffffffffu, psq[j], o);
        }
    }
    __syncthreads();
    if (g == 0) {
        #pragma unroll
        for (int nf = 0; nf < 8; nf++)
            #pragma unroll
            for (int bc = 0; bc < 2; bc++) {
                int tl = wn * 64 + nf * 8 + tg * 2 + bc;
                swsum[wm * 128 + tl] = psum[nf * 2 + bc];
                swsq[wm * 128 + tl]  = psq[nf * 2 + bc];
            }
    }
    __syncthreads();
    if (tid < 128) {
        float s  = swsum[tid] + swsum[128 + tid] + swsum[256 + tid] + swsum[384 + tid];
        float sq = swsq[tid]  + swsq[128 + tid]  + swsq[256 + tid]  + swsq[384 + tid];
        float mean = s * (1.f / 256.f);
        float var  = sq * (1.f / 256.f) - mean * mean;
        smean[tid] = mean;
        srstd[tid] = rsqrtf(var + 1e-5f);
    }
    __syncthreads();

    float* outp = y + (size_t)b * C * HW;
    #pragma unroll
    for (int mf = 0; mf < 4; mf++) {
        int o0r = wm * 64 + mf * 16 + g;
        float b0 = sbias[o0r],   g0 = slg[o0r],   be0 = slb[o0r];
        float b1 = sbias[o0r+8], g1 = slg[o0r+8], be1 = slb[o0r+8];
        #pragma unroll
        for (int nf = 0; nf < 8; nf++) {
            int tl = wn * 64 + nf * 8 + tg * 2;
            float m0 = smean[tl], m1 = smean[tl + 1];
            float r0 = srstd[tl], r1 = srstd[tl + 1];
            float2 v0, v1;
            v0.x = (acc[mf][nf][0] + b0 - m0) * r0 * g0 + be0;
            v0.y = (acc[mf][nf][1] + b0 - m1) * r1 * g0 + be0;
            v1.x = (acc[mf][nf][2] + b1 - m0) * r0 * g1 + be1;
            v1.y = (acc[mf][nf][3] + b1 - m1) * r1 * g1 + be1;
            *(float2*)(outp + (size_t)o0r * HW + t0 + tl)       = v0;
            *(float2*)(outp + (size_t)(o0r + 8) * HW + t0 + tl) = v1;
        }
    }
}

// =====================================================================
extern "C" void kernel_launch(void* const* d_in, const int* in_sizes, int n_in,
                              void* d_out, int out_size)
{
    const float* x    = (const float*)d_in[0];
    const float* mem  = (const float*)d_in[1];
    const float* Wqkv = (const float*)d_in[2];
    const float* Wout = (const float*)d_in[3];
    const float* bout = (const float*)d_in[4];
    const float* lng  = (const float*)d_in[5];
    const float* lnb  = (const float*)d_in[6];
    float* y = (float*)d_out;

    cudaFuncSetAttribute(gemm_qkv,    cudaFuncAttributeMaxDynamicSharedMemorySize, QKV_DYN);
    cudaFuncSetAttribute(gemm_out_ln, cudaFuncAttributeMaxDynamicSharedMemorySize, OUT_SMEM);

    gemm_qkv<<<dim3(NTILES, 12, B), 256, QKV_DYN>>>(x, mem, Wqkv);
    k_stats_reduce<<<32, 256>>>();
    ctx_reduce<<<512, 256>>>();
    ctx_fold<<<dim3(4, NHEADS, B), 256>>>(Wout);
    gemm_out_ln<<<dim3(HW / 128, 1, B), 256, OUT_SMEM>>>(bout, lng, lnb, y);
}